// round 5
// baseline (speedup 1.0000x reference)
#include <cuda_runtime.h>
#include <math.h>

// Problem constants
#define NB    4
#define NLQ   1024
#define NC    256
#define NH    8
#define NDH   32
#define NDFF  1024
#define NLSRC 21760

// Scratch layout (floats)
#define OFF_QK    0ll
#define OFF_QKB   1048576ll            // 4096 x 512 fused q|k
#define OFF_V     3145728ll
#define OFF_ATT   4194304ll
#define OFF_TMP   5242880ll
#define OFF_TGT1  6291456ll
#define OFF_X     7340032ll
#define OFF_OFFAW 8388608ll            // 4096 x 384 (off 0..255 | aw 256..383)
#define OFF_SAMP  10485760ll
#define OFF_TGT2  11534336ll
#define OFF_FFN1  12582912ll           // 4M
#define OFF_WCAT  16777216ll           // 384*256 + 384
#define OFF_VAL   16908288ll           // 22282240
#define OFF_SC    39190528ll           // 33554432
#define SCRATCH_TOTAL (OFF_SC + 33554432ll)

__device__ float g_scratch[SCRATCH_TOTAL];

// ---------------- packed fp32x2 FMA (Blackwell FFMA2) ----------------
union U64f2 { float2 f2; unsigned long long u; };
__device__ __forceinline__ float2 ffma2(float2 a, float2 b, float2 c) {
    U64f2 A, B, C, D;
    A.f2 = a; B.f2 = b; C.f2 = c;
    asm("fma.rn.f32x2 %0, %1, %2, %3;" : "=l"(D.u) : "l"(A.u), "l"(B.u), "l"(C.u));
    return D.f2;
}

// ---------------- elementwise add ----------------
__global__ void add_k(const float* __restrict__ a, const float* __restrict__ b,
                      float* __restrict__ o, int n) {
    int i = blockIdx.x * blockDim.x + threadIdx.x;
    if (i < n) o[i] = a[i] + b[i];
}

// ---------------- weight concat (off_w | aw_w) + biases ----------------
__global__ void wcat_k(const float* __restrict__ off_w, const float* __restrict__ aw_w,
                       const float* __restrict__ off_b, const float* __restrict__ aw_b,
                       float* __restrict__ wcat) {
    int i = blockIdx.x * blockDim.x + threadIdx.x;
    if (i < 384 * 256) {
        int row = i >> 8, col = i & 255;
        wcat[i] = (row < 256) ? off_w[row * 256 + col] : aw_w[(row - 256) * 256 + col];
    } else if (i < 384 * 256 + 384) {
        int j = i - 384 * 256;
        wcat[i] = (j < 256) ? off_b[j] : aw_b[j - 256];
    }
}

// ---------------- block reduce helpers (256 threads) ----------------
__device__ __forceinline__ float blockSum256(float v, float* sm) {
    #pragma unroll
    for (int o = 16; o > 0; o >>= 1) v += __shfl_xor_sync(0xffffffffu, v, o);
    __syncthreads();
    if ((threadIdx.x & 31) == 0) sm[threadIdx.x >> 5] = v;
    __syncthreads();
    return sm[0] + sm[1] + sm[2] + sm[3] + sm[4] + sm[5] + sm[6] + sm[7];
}
__device__ __forceinline__ float blockMax256(float v, float* sm) {
    #pragma unroll
    for (int o = 16; o > 0; o >>= 1) v = fmaxf(v, __shfl_xor_sync(0xffffffffu, v, o));
    __syncthreads();
    if ((threadIdx.x & 31) == 0) sm[threadIdx.x >> 5] = v;
    __syncthreads();
    float r = sm[0];
    #pragma unroll
    for (int i = 1; i < 8; i++) r = fmaxf(r, sm[i]);
    return r;
}

// ---------------- tiled GEMM with packed f32x2 inner loop ----------------
// C = alpha * A @ op(B) + bias, optional relu.
// TRANSB: B is [N,K] row-major (weights). !TRANSB: B is [K,N] row-major.
// Batched via blockIdx.z: z -> (zo=z/zdiv, zi=z%zdiv) with per-level strides.
// BK = 16 fixed. M%BM==0, N%BN==0, K%16==0 guaranteed by caller. TN even.
template<int BM, int BN, int TM, int TN, int NT, bool TRANSB, bool RELU>
__global__ void __launch_bounds__(NT, 2)
gemm_k(const float* __restrict__ A, const float* __restrict__ Bm,
       const float* __restrict__ bias, float* __restrict__ C,
       int K, int lda, int ldb, int ldc,
       int zdiv, long sA0, long sA1, long sB0, long sB1, long sC0, long sC1,
       float alpha)
{
    constexpr int TX = BN / TN;
    constexpr int TY = BM / TM;
    static_assert(TX * TY == NT, "thread count mismatch");
    static_assert((TN & 1) == 0, "TN must be even");

    __shared__ float2 As2[16][BM + 2];   // duplicated A: (a,a)
    __shared__ float  Bs[16][BN + 4];

    const int z = blockIdx.z;
    const long zo = z / zdiv, zi = z % zdiv;
    A  += zo * sA0 + zi * sA1;
    Bm += zo * sB0 + zi * sB1;
    C  += zo * sC0 + zi * sC1;

    const int m0 = blockIdx.x * BM;
    const int n0 = blockIdx.y * BN;
    const int t  = threadIdx.x;
    const int tx = t % TX, ty = t / TX;

    float2 acc[TM][TN / 2];
    #pragma unroll
    for (int i = 0; i < TM; i++)
        #pragma unroll
        for (int j = 0; j < TN / 2; j++) acc[i][j] = make_float2(0.f, 0.f);

    for (int k0 = 0; k0 < K; k0 += 16) {
        #pragma unroll
        for (int i = 0; i < (BM * 16) / NT; i++) {
            int idx = t + i * NT;
            int r = idx >> 4, c = idx & 15;
            float v = A[(long)(m0 + r) * lda + (k0 + c)];
            As2[c][r] = make_float2(v, v);
        }
        if (TRANSB) {
            #pragma unroll
            for (int i = 0; i < (BN * 16) / NT; i++) {
                int idx = t + i * NT;
                int r = idx >> 4, c = idx & 15;
                Bs[c][r] = Bm[(long)(n0 + r) * ldb + (k0 + c)];
            }
        } else {
            #pragma unroll
            for (int i = 0; i < (BN * 16) / NT; i++) {
                int idx = t + i * NT;
                int kk = idx / BN, nn = idx % BN;
                Bs[kk][nn] = Bm[(long)(k0 + kk) * ldb + (n0 + nn)];
            }
        }
        __syncthreads();
        #pragma unroll
        for (int kk = 0; kk < 16; kk++) {
            float2 a2[TM], b2[TN / 2];
            #pragma unroll
            for (int i = 0; i < TM; i++) a2[i] = As2[kk][ty * TM + i];
            #pragma unroll
            for (int j = 0; j < TN / 2; j++)
                b2[j] = *(const float2*)&Bs[kk][tx * TN + 2 * j];
            #pragma unroll
            for (int i = 0; i < TM; i++)
                #pragma unroll
                for (int j = 0; j < TN / 2; j++)
                    acc[i][j] = ffma2(a2[i], b2[j], acc[i][j]);
        }
        __syncthreads();
    }

    #pragma unroll
    for (int i = 0; i < TM; i++) {
        float* crow = C + (long)(m0 + ty * TM + i) * ldc + n0 + tx * TN;
        #pragma unroll
        for (int j = 0; j < TN / 2; j++) {
            float2 v = acc[i][j];
            v.x *= alpha; v.y *= alpha;
            if (bias) {
                v.x += bias[n0 + tx * TN + 2 * j];
                v.y += bias[n0 + tx * TN + 2 * j + 1];
            }
            if (RELU) { v.x = fmaxf(v.x, 0.f); v.y = fmaxf(v.y, 0.f); }
            *(float2*)(crow + 2 * j) = v;
        }
    }
}

// ---------------- row softmax over 1024-wide rows ----------------
__global__ void softmax_k(float* __restrict__ S) {
    __shared__ float sm[8];
    float* row = S + (long)blockIdx.x * 1024;
    int t = threadIdx.x;
    float v[4];
    float mx = -3.4e38f;
    #pragma unroll
    for (int i = 0; i < 4; i++) { v[i] = row[t + i * 256]; mx = fmaxf(mx, v[i]); }
    mx = blockMax256(mx, sm);
    float s = 0.f;
    #pragma unroll
    for (int i = 0; i < 4; i++) { v[i] = __expf(v[i] - mx); s += v[i]; }
    s = blockSum256(s, sm);
    float inv = 1.f / s;
    #pragma unroll
    for (int i = 0; i < 4; i++) row[t + i * 256] = v[i] * inv;
}

// ---------------- residual + layernorm (+ optional out2 = ln + pos) ----------------
__global__ void resln_k(const float* __restrict__ a, const float* __restrict__ b,
                        const float* __restrict__ g, const float* __restrict__ be,
                        float* __restrict__ out,
                        const float* __restrict__ pos, float* __restrict__ out2)
{
    __shared__ float sm[8];
    int row = blockIdx.x, t = threadIdx.x;
    long off = (long)row * NC + t;
    float x = a[off] + b[off];
    float m = blockSum256(x, sm) * (1.f / NC);
    float d = x - m;
    float v = blockSum256(d * d, sm) * (1.f / NC);
    float y = d * rsqrtf(v + 1e-5f) * g[t] + be[t];
    out[off] = y;
    if (out2) out2[off] = y + pos[off];
}

// ---------------- deformable sampling (one warp per (b,q,h), lanes = DH) ----------------
// offaw layout per (b,q): 384 floats = [h][l][p][2] offsets (256) | [h][l*p] aw logits (128)
__global__ void deform_k(const float* __restrict__ value,
                         const float* __restrict__ offaw,
                         const float* __restrict__ refp,
                         float* __restrict__ out)
{
    int gw   = (blockIdx.x * blockDim.x + threadIdx.x) >> 5;
    int lane = threadIdx.x & 31;
    int h  = gw & 7;
    int bq = gw >> 3;
    int b  = bq >> 10;

    const float* ap = offaw + (long)bq * 384 + 256 + h * 16;
    float w[16];
    float mx = -3.4e38f;
    #pragma unroll
    for (int j = 0; j < 16; j++) { w[j] = ap[j]; mx = fmaxf(mx, w[j]); }
    float s = 0.f;
    #pragma unroll
    for (int j = 0; j < 16; j++) { w[j] = __expf(w[j] - mx); s += w[j]; }
    float inv = 1.f / s;

    const float* op = offaw + (long)bq * 384 + h * 32;
    const float* rp = refp + (long)bq * 8;
    const float* vb = value + (long)b * NLSRC * NC + h * NDH + lane;

    const int wl_[4] = {128, 64, 32, 16};
    const int st_[4] = {0, 16384, 20480, 21504};

    float acc = 0.f;
    #pragma unroll
    for (int l = 0; l < 4; l++) {
        const int W = wl_[l], Hh = wl_[l];
        const int st = st_[l];
        float rx = rp[l * 2 + 0] * (float)W  - 0.5f;
        float ry = rp[l * 2 + 1] * (float)Hh - 0.5f;
        #pragma unroll
        for (int p = 0; p < 4; p++) {
            float a = w[l * 4 + p] * inv;
            float x = rx + op[(l * 4 + p) * 2 + 0];
            float y = ry + op[(l * 4 + p) * 2 + 1];
            float xf = floorf(x), yf = floorf(y);
            int x0 = (int)xf, y0 = (int)yf;
            float wx1 = x - xf, wy1 = y - yf;
            float wx0 = 1.f - wx1, wy0 = 1.f - wy1;
            #pragma unroll
            for (int cy = 0; cy < 2; cy++) {
                int iy = y0 + cy;
                if (iy < 0 || iy >= Hh) continue;
                float wy = cy ? wy1 : wy0;
                #pragma unroll
                for (int cx = 0; cx < 2; cx++) {
                    int ix = x0 + cx;
                    if (ix < 0 || ix >= W) continue;
                    float cw = a * wy * (cx ? wx1 : wx0);
                    acc += cw * vb[(long)(st + iy * W + ix) * NC];
                }
            }
        }
    }
    out[(long)bq * NC + h * NDH + lane] = acc;
}

extern "C" void kernel_launch(void* const* d_in, const int* in_sizes, int n_in,
                              void* d_out, int out_size)
{
    const float* tgt   = (const float*)d_in[0];
    const float* qpos  = (const float*)d_in[1];
    const float* refp  = (const float*)d_in[2];
    const float* src   = (const float*)d_in[3];
    const float* in_w  = (const float*)d_in[4];
    const float* in_b  = (const float*)d_in[5];
    const float* sa_w  = (const float*)d_in[6];
    const float* sa_b  = (const float*)d_in[7];
    const float* off_w = (const float*)d_in[8];
    const float* off_b = (const float*)d_in[9];
    const float* aw_w  = (const float*)d_in[10];
    const float* aw_b  = (const float*)d_in[11];
    const float* val_w = (const float*)d_in[12];
    const float* val_b = (const float*)d_in[13];
    const float* co_w  = (const float*)d_in[14];
    const float* co_b  = (const float*)d_in[15];
    const float* ln1_g = (const float*)d_in[16];
    const float* ln1_b = (const float*)d_in[17];
    const float* ln2_g = (const float*)d_in[18];
    const float* ln2_b = (const float*)d_in[19];
    const float* ln3_g = (const float*)d_in[20];
    const float* ln3_b = (const float*)d_in[21];
    const float* f1_w  = (const float*)d_in[22];
    const float* f1_b  = (const float*)d_in[23];
    const float* f2_w  = (const float*)d_in[24];
    const float* f2_b  = (const float*)d_in[25];

    float* S = nullptr;
    cudaGetSymbolAddress((void**)&S, g_scratch);

    float* qk    = S + OFF_QK;
    float* qkb   = S + OFF_QKB;    // [4096, 512]: q | k
    float* vb    = S + OFF_V;
    float* att   = S + OFF_ATT;
    float* tmp   = S + OFF_TMP;
    float* tgt1  = S + OFF_TGT1;
    float* xq    = S + OFF_X;
    float* offaw = S + OFF_OFFAW;  // [4096, 384]
    float* samp  = S + OFF_SAMP;
    float* tgt2  = S + OFF_TGT2;
    float* ffn1  = S + OFF_FFN1;
    float* wcat  = S + OFF_WCAT;   // [384,256] weights + 384 bias
    float* valb  = S + OFF_VAL;
    float* sc    = S + OFF_SC;

    const float scale = 0.1767766952966369f; // 1/sqrt(32)

    // ---- self-attention ----
    add_k<<<4096, 256>>>(tgt, qpos, qk, NB * NLQ * NC);
    wcat_k<<<(384 * 256 + 384 + 255) / 256, 256>>>(off_w, aw_w, off_b, aw_b, wcat);

    // fused q|k projection: M=4096, N=512, K=256
    gemm_k<128,64,8,4,256,true,false><<<dim3(32,8,1), 256>>>(
        qk, in_w, in_b, qkb, 256, 256, 256, 512, 1,0,0,0,0,0,0, 1.f);
    // v projection: M=4096, N=256
    gemm_k<128,64,8,4,256,true,false><<<dim3(32,4,1), 256>>>(
        tgt, in_w + 131072, in_b + 512, vb, 256, 256, 256, 256, 1,0,0,0,0,0,0, 1.f);

    // scores[b,h] = scale * Q K^T  (M=N=1024, K=32, z = b*8+h)
    gemm_k<128,64,8,4,256,true,false><<<dim3(8,16,32), 256>>>(
        qkb, qkb + 256, nullptr, sc, 32, 512, 512, 1024,
        8, 524288ll, 32ll, 524288ll, 32ll, 8388608ll, 1048576ll, scale);

    softmax_k<<<32768, 256>>>(sc);

    // O[b,h] = P @ V  (M=1024, N=32, K=1024)
    gemm_k<128,32,8,4,128,false,false><<<dim3(8,1,32), 128>>>(
        sc, vb, nullptr, att, 1024, 1024, 256, 256,
        8, 8388608ll, 1048576ll, 262144ll, 32ll, 262144ll, 32ll, 1.f);

    // out projection + residual + LN2 (also x = ln_out + pos)
    gemm_k<128,64,8,4,256,true,false><<<dim3(32,4,1), 256>>>(
        att, sa_w, sa_b, tmp, 256, 256, 256, 256, 1,0,0,0,0,0,0, 1.f);
    resln_k<<<4096, 256>>>(tgt, tmp, ln2_g, ln2_b, tgt1, qpos, xq);

    // ---- deformable cross-attention ----
    // value = src @ val_w^T + val_b  (M=87040)
    gemm_k<128,64,8,4,256,true,false><<<dim3(680,4,1), 256>>>(
        src, val_w, val_b, valb, 256, 256, 256, 256, 1,0,0,0,0,0,0, 1.f);
    // fused offsets + aw logits: N=384
    gemm_k<128,64,8,4,256,true,false><<<dim3(32,6,1), 256>>>(
        xq, wcat, wcat + 384 * 256, offaw, 256, 256, 256, 384, 1,0,0,0,0,0,0, 1.f);

    deform_k<<<4096, 256>>>(valb, offaw, refp, samp);

    gemm_k<128,64,8,4,256,true,false><<<dim3(32,4,1), 256>>>(
        samp, co_w, co_b, tmp, 256, 256, 256, 256, 1,0,0,0,0,0,0, 1.f);
    resln_k<<<4096, 256>>>(tgt1, tmp, ln1_g, ln1_b, tgt2, nullptr, nullptr);

    // ---- FFN ----
    gemm_k<128,64,8,4,256,true,true ><<<dim3(32,16,1), 256>>>(
        tgt2, f1_w, f1_b, ffn1, 256, 256, 256, 1024, 1,0,0,0,0,0,0, 1.f);
    gemm_k<128,64,8,4,256,true,false><<<dim3(32,4,1), 256>>>(
        ffn1, f2_w, f2_b, tmp, 1024, 1024, 1024, 256, 1,0,0,0,0,0,0, 1.f);
    resln_k<<<4096, 256>>>(tgt2, tmp, ln3_g, ln3_b, (float*)d_out, nullptr, nullptr);
}

// round 6
// speedup vs baseline: 1.0964x; 1.0964x over previous
#include <cuda_runtime.h>
#include <math.h>

// Problem constants
#define NB    4
#define NLQ   1024
#define NC    256
#define NH    8
#define NDH   32
#define NDFF  1024
#define NLSRC 21760

// Scratch layout (floats)
#define OFF_QK    0ll
#define OFF_QKB   1048576ll            // 4096 x 512 fused q|k
#define OFF_V     3145728ll
#define OFF_ATT   4194304ll
#define OFF_TMP   5242880ll
#define OFF_TGT1  6291456ll
#define OFF_X     7340032ll
#define OFF_OFFAW 8388608ll            // 4096 x 384 (off 0..255 | aw 256..383)
#define OFF_SAMP  10485760ll
#define OFF_TGT2  11534336ll
#define OFF_FFN1  12582912ll           // 4M
#define OFF_WCAT  16777216ll           // 384*256 + 384
#define OFF_VAL   16908288ll           // 22282240
#define SCRATCH_TOTAL (OFF_VAL + 22282240ll)

__device__ float g_scratch[SCRATCH_TOTAL];

// ---------------- packed fp32x2 FMA (Blackwell FFMA2) ----------------
union U64f2 { float2 f2; unsigned long long u; };
__device__ __forceinline__ float2 ffma2(float2 a, float2 b, float2 c) {
    U64f2 A, B, C, D;
    A.f2 = a; B.f2 = b; C.f2 = c;
    asm("fma.rn.f32x2 %0, %1, %2, %3;" : "=l"(D.u) : "l"(A.u), "l"(B.u), "l"(C.u));
    return D.f2;
}

// ---------------- elementwise add ----------------
__global__ void add_k(const float* __restrict__ a, const float* __restrict__ b,
                      float* __restrict__ o, int n) {
    int i = blockIdx.x * blockDim.x + threadIdx.x;
    if (i < n) o[i] = a[i] + b[i];
}

// ---------------- weight concat (off_w | aw_w) + biases ----------------
__global__ void wcat_k(const float* __restrict__ off_w, const float* __restrict__ aw_w,
                       const float* __restrict__ off_b, const float* __restrict__ aw_b,
                       float* __restrict__ wcat) {
    int i = blockIdx.x * blockDim.x + threadIdx.x;
    if (i < 384 * 256) {
        int row = i >> 8, col = i & 255;
        wcat[i] = (row < 256) ? off_w[row * 256 + col] : aw_w[(row - 256) * 256 + col];
    } else if (i < 384 * 256 + 384) {
        int j = i - 384 * 256;
        wcat[i] = (j < 256) ? off_b[j] : aw_b[j - 256];
    }
}

// ---------------- block reduce helpers (256 threads) ----------------
__device__ __forceinline__ float blockSum256(float v, float* sm) {
    #pragma unroll
    for (int o = 16; o > 0; o >>= 1) v += __shfl_xor_sync(0xffffffffu, v, o);
    __syncthreads();
    if ((threadIdx.x & 31) == 0) sm[threadIdx.x >> 5] = v;
    __syncthreads();
    return sm[0] + sm[1] + sm[2] + sm[3] + sm[4] + sm[5] + sm[6] + sm[7];
}

// ---------------- double-buffered tiled GEMM, f32x2 inner loop ----------------
// C = alpha * A @ op(B) + bias, optional relu.
// TRANSB: B is [N,K] row-major (weights). Grid: x = N tiles, y = M tiles, z batch.
// BK = 16 fixed. M%BM==0, N%BN==0, K%16==0, K>=32.
template<int BM, int BN, int TM, int TN, int NT, bool TRANSB, bool RELU>
__global__ void __launch_bounds__(NT, 2)
gemm_k(const float* __restrict__ A, const float* __restrict__ Bm,
       const float* __restrict__ bias, float* __restrict__ C,
       int K, int lda, int ldb, int ldc,
       int zdiv, long sA0, long sA1, long sB0, long sB1, long sC0, long sC1,
       float alpha)
{
    constexpr int TX = BN / TN;
    constexpr int TY = BM / TM;
    constexpr int AREG = BM * 16 / NT;
    constexpr int BREG = BN * 16 / NT;
    static_assert(TX * TY == NT, "thread count mismatch");
    static_assert((TN & 1) == 0, "TN must be even");

    __shared__ float2 As2[2][16][BM + 2];   // duplicated A: (a,a)
    __shared__ float  Bs[2][16][BN + 4];

    const int z = blockIdx.z;
    const long zo = z / zdiv, zi = z % zdiv;
    A  += zo * sA0 + zi * sA1;
    Bm += zo * sB0 + zi * sB1;
    C  += zo * sC0 + zi * sC1;

    const int m0 = blockIdx.y * BM;
    const int n0 = blockIdx.x * BN;
    const int t  = threadIdx.x;
    const int tx = t % TX, ty = t / TX;

    float2 acc[TM][TN / 2];
    #pragma unroll
    for (int i = 0; i < TM; i++)
        #pragma unroll
        for (int j = 0; j < TN / 2; j++) acc[i][j] = make_float2(0.f, 0.f);

    float ar[AREG], br[BREG];

    // prologue: tile 0
    #pragma unroll
    for (int i = 0; i < AREG; i++) {
        int idx = t + i * NT;
        int r = idx >> 4, c = idx & 15;
        ar[i] = A[(long)(m0 + r) * lda + c];
    }
    #pragma unroll
    for (int i = 0; i < BREG; i++) {
        int idx = t + i * NT;
        if (TRANSB) {
            int r = idx >> 4, c = idx & 15;
            br[i] = Bm[(long)(n0 + r) * ldb + c];
        } else {
            int kk = idx / BN, nn = idx % BN;
            br[i] = Bm[(long)kk * ldb + (n0 + nn)];
        }
    }
    #pragma unroll
    for (int i = 0; i < AREG; i++) {
        int idx = t + i * NT;
        int r = idx >> 4, c = idx & 15;
        As2[0][c][r] = make_float2(ar[i], ar[i]);
    }
    #pragma unroll
    for (int i = 0; i < BREG; i++) {
        int idx = t + i * NT;
        if (TRANSB) { int r = idx >> 4, c = idx & 15; Bs[0][c][r] = br[i]; }
        else        { int kk = idx / BN, nn = idx % BN; Bs[0][kk][nn] = br[i]; }
    }
    __syncthreads();

    const int nt = K >> 4;
    for (int tt = 0; tt < nt; tt++) {
        const int cur = tt & 1;
        const int k1 = (tt + 1) << 4;
        if (tt + 1 < nt) {
            #pragma unroll
            for (int i = 0; i < AREG; i++) {
                int idx = t + i * NT;
                int r = idx >> 4, c = idx & 15;
                ar[i] = A[(long)(m0 + r) * lda + (k1 + c)];
            }
            #pragma unroll
            for (int i = 0; i < BREG; i++) {
                int idx = t + i * NT;
                if (TRANSB) {
                    int r = idx >> 4, c = idx & 15;
                    br[i] = Bm[(long)(n0 + r) * ldb + (k1 + c)];
                } else {
                    int kk = idx / BN, nn = idx % BN;
                    br[i] = Bm[(long)(k1 + kk) * ldb + (n0 + nn)];
                }
            }
        }
        #pragma unroll
        for (int kk = 0; kk < 16; kk++) {
            float2 a2[TM], b2[TN / 2];
            #pragma unroll
            for (int i = 0; i < TM; i++) a2[i] = As2[cur][kk][ty * TM + i];
            #pragma unroll
            for (int j = 0; j < TN / 2; j++)
                b2[j] = *(const float2*)&Bs[cur][kk][tx * TN + 2 * j];
            #pragma unroll
            for (int i = 0; i < TM; i++)
                #pragma unroll
                for (int j = 0; j < TN / 2; j++)
                    acc[i][j] = ffma2(a2[i], b2[j], acc[i][j]);
        }
        if (tt + 1 < nt) {
            const int nxt = cur ^ 1;
            #pragma unroll
            for (int i = 0; i < AREG; i++) {
                int idx = t + i * NT;
                int r = idx >> 4, c = idx & 15;
                As2[nxt][c][r] = make_float2(ar[i], ar[i]);
            }
            #pragma unroll
            for (int i = 0; i < BREG; i++) {
                int idx = t + i * NT;
                if (TRANSB) { int r = idx >> 4, c = idx & 15; Bs[nxt][c][r] = br[i]; }
                else        { int kk = idx / BN, nn = idx % BN; Bs[nxt][kk][nn] = br[i]; }
            }
        }
        __syncthreads();
    }

    #pragma unroll
    for (int i = 0; i < TM; i++) {
        float* crow = C + (long)(m0 + ty * TM + i) * ldc + n0 + tx * TN;
        #pragma unroll
        for (int j = 0; j < TN / 2; j++) {
            float2 v = acc[i][j];
            v.x *= alpha; v.y *= alpha;
            if (bias) {
                v.x += bias[n0 + tx * TN + 2 * j];
                v.y += bias[n0 + tx * TN + 2 * j + 1];
            }
            if (RELU) { v.x = fmaxf(v.x, 0.f); v.y = fmaxf(v.y, 0.f); }
            *(float2*)(crow + 2 * j) = v;
        }
    }
}

// ---------------- flash attention (fp32, online softmax) ----------------
// Block: 256 threads, one (b,h), 64 q rows. grid = dim3(16, 1, 32), z = b*8+h.
// qkb: [4096,512] rows bq, cols: q at h*32, k at 256+h*32. vb: [4096,256].
// out: [4096,256] at h*32. Q is pre-scaled by 1/sqrt(32).
__global__ void __launch_bounds__(256, 2)
flash_k(const float* __restrict__ qkb, const float* __restrict__ vb,
        float* __restrict__ out)
{
    __shared__ float Qs[64][36];
    __shared__ float Kt[32][68];   // transposed: [dh][kv]
    __shared__ float Vs[64][36];
    __shared__ float Ps[64][66];

    const int z = blockIdx.z;
    const int b = z >> 3, h = z & 7;
    const int q0 = blockIdx.x * 64;
    const int t = threadIdx.x;
    const int tx = t & 15, ty = t >> 4;

    const float* Qg = qkb + ((long)(b * 1024 + q0)) * 512 + h * 32;
    const float* Kg = qkb + (long)b * 1024 * 512 + 256 + h * 32;
    const float* Vg = vb + (long)b * 1024 * 256 + h * 32;

    const float scale = 0.1767766952966369f;

    // load Q tile (scaled)
    {
        int r = t >> 2, c0 = (t & 3) * 8;
        float4 v0 = *(const float4*)(Qg + (long)r * 512 + c0);
        float4 v1 = *(const float4*)(Qg + (long)r * 512 + c0 + 4);
        v0.x *= scale; v0.y *= scale; v0.z *= scale; v0.w *= scale;
        v1.x *= scale; v1.y *= scale; v1.z *= scale; v1.w *= scale;
        *(float4*)&Qs[r][c0] = v0;
        *(float4*)&Qs[r][c0 + 4] = v1;
    }

    float m[4], l[4];
    float2 o[4];
    #pragma unroll
    for (int i = 0; i < 4; i++) { m[i] = -3.4e38f; l[i] = 0.f; o[i] = make_float2(0.f, 0.f); }

    for (int kv0 = 0; kv0 < 1024; kv0 += 64) {
        // load K chunk transposed + V chunk
        {
            int r = t >> 2, c0 = (t & 3) * 8;
            const float* kp = Kg + (long)(kv0 + r) * 512 + c0;
            float4 a = *(const float4*)kp;
            float4 bb = *(const float4*)(kp + 4);
            Kt[c0 + 0][r] = a.x;  Kt[c0 + 1][r] = a.y;
            Kt[c0 + 2][r] = a.z;  Kt[c0 + 3][r] = a.w;
            Kt[c0 + 4][r] = bb.x; Kt[c0 + 5][r] = bb.y;
            Kt[c0 + 6][r] = bb.z; Kt[c0 + 7][r] = bb.w;
            const float* vp = Vg + (long)(kv0 + r) * 256 + c0;
            *(float4*)&Vs[r][c0]     = *(const float4*)vp;
            *(float4*)&Vs[r][c0 + 4] = *(const float4*)(vp + 4);
        }
        __syncthreads();

        // S tile: 4q x 4kv per thread
        float2 acc[4][2];
        #pragma unroll
        for (int i = 0; i < 4; i++) { acc[i][0] = make_float2(0.f, 0.f); acc[i][1] = make_float2(0.f, 0.f); }
        #pragma unroll
        for (int kk = 0; kk < 32; kk++) {
            float4 b4 = *(const float4*)&Kt[kk][tx * 4];
            float2 blo = make_float2(b4.x, b4.y);
            float2 bhi = make_float2(b4.z, b4.w);
            #pragma unroll
            for (int i = 0; i < 4; i++) {
                float a = Qs[ty * 4 + i][kk];
                float2 a2 = make_float2(a, a);
                acc[i][0] = ffma2(a2, blo, acc[i][0]);
                acc[i][1] = ffma2(a2, bhi, acc[i][1]);
            }
        }

        // online softmax update per q row
        #pragma unroll
        for (int i = 0; i < 4; i++) {
            float s0 = acc[i][0].x, s1 = acc[i][0].y, s2 = acc[i][1].x, s3 = acc[i][1].y;
            float mx = fmaxf(fmaxf(s0, s1), fmaxf(s2, s3));
            #pragma unroll
            for (int off = 1; off < 16; off <<= 1)
                mx = fmaxf(mx, __shfl_xor_sync(0xffffffffu, mx, off));
            float mnew = fmaxf(m[i], mx);
            float p0 = __expf(s0 - mnew), p1 = __expf(s1 - mnew);
            float p2 = __expf(s2 - mnew), p3 = __expf(s3 - mnew);
            float rs = p0 + p1 + p2 + p3;
            #pragma unroll
            for (int off = 1; off < 16; off <<= 1)
                rs += __shfl_xor_sync(0xffffffffu, rs, off);
            float sc_ = __expf(m[i] - mnew);
            l[i] = l[i] * sc_ + rs;
            o[i].x *= sc_; o[i].y *= sc_;
            m[i] = mnew;
            float* pr = &Ps[ty * 4 + i][tx * 4];
            pr[0] = p0; pr[1] = p1; pr[2] = p2; pr[3] = p3;
        }
        __syncthreads();

        // O += P @ V  (each thread: 4q x 2dh)
        #pragma unroll 4
        for (int kv = 0; kv < 64; kv++) {
            float2 v2 = *(const float2*)&Vs[kv][tx * 2];
            #pragma unroll
            for (int i = 0; i < 4; i++) {
                float p = Ps[ty * 4 + i][kv];
                o[i] = ffma2(make_float2(p, p), v2, o[i]);
            }
        }
        __syncthreads();
    }

    #pragma unroll
    for (int i = 0; i < 4; i++) {
        float inv = 1.f / l[i];
        float2 r = make_float2(o[i].x * inv, o[i].y * inv);
        *(float2*)(out + ((long)(b * 1024 + q0 + ty * 4 + i)) * 256 + h * 32 + tx * 2) = r;
    }
}

// ---------------- residual + layernorm (+ optional out2 = ln + pos) ----------------
__global__ void resln_k(const float* __restrict__ a, const float* __restrict__ b,
                        const float* __restrict__ g, const float* __restrict__ be,
                        float* __restrict__ out,
                        const float* __restrict__ pos, float* __restrict__ out2)
{
    __shared__ float sm[8];
    int row = blockIdx.x, t = threadIdx.x;
    long off = (long)row * NC + t;
    float x = a[off] + b[off];
    float mn = blockSum256(x, sm) * (1.f / NC);
    float d = x - mn;
    float v = blockSum256(d * d, sm) * (1.f / NC);
    float y = d * rsqrtf(v + 1e-5f) * g[t] + be[t];
    out[off] = y;
    if (out2) out2[off] = y + pos[off];
}

// ---------------- deformable sampling (one warp per (b,q,h), lanes = DH) ----------------
__global__ void deform_k(const float* __restrict__ value,
                         const float* __restrict__ offaw,
                         const float* __restrict__ refp,
                         float* __restrict__ out)
{
    int gw   = (blockIdx.x * blockDim.x + threadIdx.x) >> 5;
    int lane = threadIdx.x & 31;
    int h  = gw & 7;
    int bq = gw >> 3;
    int b  = bq >> 10;

    const float* ap = offaw + (long)bq * 384 + 256 + h * 16;
    float w[16];
    float mx = -3.4e38f;
    #pragma unroll
    for (int j = 0; j < 16; j++) { w[j] = ap[j]; mx = fmaxf(mx, w[j]); }
    float s = 0.f;
    #pragma unroll
    for (int j = 0; j < 16; j++) { w[j] = __expf(w[j] - mx); s += w[j]; }
    float inv = 1.f / s;

    const float* op = offaw + (long)bq * 384 + h * 32;
    const float* rp = refp + (long)bq * 8;
    const float* vb = value + (long)b * NLSRC * NC + h * NDH + lane;

    const int wl_[4] = {128, 64, 32, 16};
    const int st_[4] = {0, 16384, 20480, 21504};

    float acc = 0.f;
    #pragma unroll
    for (int l = 0; l < 4; l++) {
        const int W = wl_[l], Hh = wl_[l];
        const int st = st_[l];
        float rx = rp[l * 2 + 0] * (float)W  - 0.5f;
        float ry = rp[l * 2 + 1] * (float)Hh - 0.5f;
        #pragma unroll
        for (int p = 0; p < 4; p++) {
            float a = w[l * 4 + p] * inv;
            float x = rx + op[(l * 4 + p) * 2 + 0];
            float y = ry + op[(l * 4 + p) * 2 + 1];
            float xf = floorf(x), yf = floorf(y);
            int x0 = (int)xf, y0 = (int)yf;
            float wx1 = x - xf, wy1 = y - yf;
            float wx0 = 1.f - wx1, wy0 = 1.f - wy1;
            #pragma unroll
            for (int cy = 0; cy < 2; cy++) {
                int iy = y0 + cy;
                if (iy < 0 || iy >= Hh) continue;
                float wy = cy ? wy1 : wy0;
                #pragma unroll
                for (int cx = 0; cx < 2; cx++) {
                    int ix = x0 + cx;
                    if (ix < 0 || ix >= W) continue;
                    float cw = a * wy * (cx ? wx1 : wx0);
                    acc += cw * vb[(long)(st + iy * W + ix) * NC];
                }
            }
        }
    }
    out[(long)bq * NC + h * NDH + lane] = acc;
}

extern "C" void kernel_launch(void* const* d_in, const int* in_sizes, int n_in,
                              void* d_out, int out_size)
{
    const float* tgt   = (const float*)d_in[0];
    const float* qpos  = (const float*)d_in[1];
    const float* refp  = (const float*)d_in[2];
    const float* src   = (const float*)d_in[3];
    const float* in_w  = (const float*)d_in[4];
    const float* in_b  = (const float*)d_in[5];
    const float* sa_w  = (const float*)d_in[6];
    const float* sa_b  = (const float*)d_in[7];
    const float* off_w = (const float*)d_in[8];
    const float* off_b = (const float*)d_in[9];
    const float* aw_w  = (const float*)d_in[10];
    const float* aw_b  = (const float*)d_in[11];
    const float* val_w = (const float*)d_in[12];
    const float* val_b = (const float*)d_in[13];
    const float* co_w  = (const float*)d_in[14];
    const float* co_b  = (const float*)d_in[15];
    const float* ln1_g = (const float*)d_in[16];
    const float* ln1_b = (const float*)d_in[17];
    const float* ln2_g = (const float*)d_in[18];
    const float* ln2_b = (const float*)d_in[19];
    const float* ln3_g = (const float*)d_in[20];
    const float* ln3_b = (const float*)d_in[21];
    const float* f1_w  = (const float*)d_in[22];
    const float* f1_b  = (const float*)d_in[23];
    const float* f2_w  = (const float*)d_in[24];
    const float* f2_b  = (const float*)d_in[25];

    float* S = nullptr;
    cudaGetSymbolAddress((void**)&S, g_scratch);

    float* qk    = S + OFF_QK;
    float* qkb   = S + OFF_QKB;    // [4096, 512]: q | k
    float* vb    = S + OFF_V;
    float* att   = S + OFF_ATT;
    float* tmp   = S + OFF_TMP;
    float* tgt1  = S + OFF_TGT1;
    float* xq    = S + OFF_X;
    float* offaw = S + OFF_OFFAW;  // [4096, 384]
    float* samp  = S + OFF_SAMP;
    float* tgt2  = S + OFF_TGT2;
    float* ffn1  = S + OFF_FFN1;
    float* wcat  = S + OFF_WCAT;   // [384,256] weights + 384 bias
    float* valb  = S + OFF_VAL;

    // ---- self-attention ----
    add_k<<<4096, 256>>>(tgt, qpos, qk, NB * NLQ * NC);
    wcat_k<<<(384 * 256 + 384 + 255) / 256, 256>>>(off_w, aw_w, off_b, aw_b, wcat);

    // fused q|k projection: M=4096, N=512, K=256   (grid: x=N tiles, y=M tiles)
    gemm_k<128,64,8,4,256,true,false><<<dim3(8,32,1), 256>>>(
        qk, in_w, in_b, qkb, 256, 256, 256, 512, 1,0,0,0,0,0,0, 1.f);
    // v projection: M=4096, N=256
    gemm_k<128,64,8,4,256,true,false><<<dim3(4,32,1), 256>>>(
        tgt, in_w + 131072, in_b + 512, vb, 256, 256, 256, 256, 1,0,0,0,0,0,0, 1.f);

    // fused attention (scores + softmax + PV)
    flash_k<<<dim3(16,1,32), 256>>>(qkb, vb, att);

    // out projection + residual + LN2 (also x = ln_out + pos)
    gemm_k<128,64,8,4,256,true,false><<<dim3(4,32,1), 256>>>(
        att, sa_w, sa_b, tmp, 256, 256, 256, 256, 1,0,0,0,0,0,0, 1.f);
    resln_k<<<4096, 256>>>(tgt, tmp, ln2_g, ln2_b, tgt1, qpos, xq);

    // ---- deformable cross-attention ----
    // value = src @ val_w^T + val_b  (M=87040; N tiles fastest for L2 A-reuse)
    gemm_k<128,64,8,4,256,true,false><<<dim3(4,680,1), 256>>>(
        src, val_w, val_b, valb, 256, 256, 256, 256, 1,0,0,0,0,0,0, 1.f);
    // fused offsets + aw logits: N=384
    gemm_k<128,64,8,4,256,true,false><<<dim3(6,32,1), 256>>>(
        xq, wcat, wcat + 384 * 256, offaw, 256, 256, 256, 384, 1,0,0,0,0,0,0, 1.f);

    deform_k<<<4096, 256>>>(valb, offaw, refp, samp);

    gemm_k<128,64,8,4,256,true,false><<<dim3(4,32,1), 256>>>(
        samp, co_w, co_b, tmp, 256, 256, 256, 256, 1,0,0,0,0,0,0, 1.f);
    resln_k<<<4096, 256>>>(tgt1, tmp, ln1_g, ln1_b, tgt2, nullptr, nullptr);

    // ---- FFN ----
    gemm_k<128,64,8,4,256,true,true ><<<dim3(16,32,1), 256>>>(
        tgt2, f1_w, f1_b, ffn1, 256, 256, 256, 1024, 1,0,0,0,0,0,0, 1.f);
    gemm_k<128,64,8,4,256,true,false><<<dim3(4,32,1), 256>>>(
        ffn1, f2_w, f2_b, tmp, 1024, 1024, 1024, 256, 1,0,0,0,0,0,0, 1.f);
    resln_k<<<4096, 256>>>(tgt2, tmp, ln3_g, ln3_b, (float*)d_out, nullptr, nullptr);
}

// round 7
// speedup vs baseline: 1.1789x; 1.0753x over previous
#include <cuda_runtime.h>
#include <math.h>

// Problem constants
#define NB    4
#define NLQ   1024
#define NC    256
#define NH    8
#define NDH   32
#define NDFF  1024
#define NLSRC 21760

// Scratch layout (floats)
#define OFF_QK    0ll
#define OFF_QKB   1048576ll            // 4096 x 512 fused q|k
#define OFF_V     3145728ll
#define OFF_ATT   4194304ll
#define OFF_TMP   5242880ll
#define OFF_TGT1  6291456ll
#define OFF_X     7340032ll
#define OFF_OFFAW 8388608ll            // 4096 x 384 (off 0..255 | aw 256..383)
#define OFF_SAMP  10485760ll
#define OFF_TGT2  11534336ll
#define OFF_FFN1  12582912ll           // 4M
#define OFF_WCAT  16777216ll           // 384*256 + 384
#define OFF_VAL   16908288ll           // 22282240
#define SCRATCH_TOTAL (OFF_VAL + 22282240ll)

__device__ float g_scratch[SCRATCH_TOTAL];

// ---------------- packed fp32x2 FMA (Blackwell FFMA2) ----------------
union U64f2 { float2 f2; unsigned long long u; };
__device__ __forceinline__ float2 ffma2(float2 a, float2 b, float2 c) {
    U64f2 A, B, C, D;
    A.f2 = a; B.f2 = b; C.f2 = c;
    asm("fma.rn.f32x2 %0, %1, %2, %3;" : "=l"(D.u) : "l"(A.u), "l"(B.u), "l"(C.u));
    return D.f2;
}

// ---------------- elementwise add ----------------
__global__ void add_k(const float* __restrict__ a, const float* __restrict__ b,
                      float* __restrict__ o, int n) {
    int i = blockIdx.x * blockDim.x + threadIdx.x;
    if (i < n) o[i] = a[i] + b[i];
}

// ---------------- weight concat (off_w | aw_w) + biases ----------------
__global__ void wcat_k(const float* __restrict__ off_w, const float* __restrict__ aw_w,
                       const float* __restrict__ off_b, const float* __restrict__ aw_b,
                       float* __restrict__ wcat) {
    int i = blockIdx.x * blockDim.x + threadIdx.x;
    if (i < 384 * 256) {
        int row = i >> 8, col = i & 255;
        wcat[i] = (row < 256) ? off_w[row * 256 + col] : aw_w[(row - 256) * 256 + col];
    } else if (i < 384 * 256 + 384) {
        int j = i - 384 * 256;
        wcat[i] = (j < 256) ? off_b[j] : aw_b[j - 256];
    }
}

// ---------------- block reduce helper (256 threads) ----------------
__device__ __forceinline__ float blockSum256(float v, float* sm) {
    #pragma unroll
    for (int o = 16; o > 0; o >>= 1) v += __shfl_xor_sync(0xffffffffu, v, o);
    __syncthreads();
    if ((threadIdx.x & 31) == 0) sm[threadIdx.x >> 5] = v;
    __syncthreads();
    return sm[0] + sm[1] + sm[2] + sm[3] + sm[4] + sm[5] + sm[6] + sm[7];
}

// ---------------- GEMM v1: 128x64 tile, duplicated-A f32x2 (for small N) ----------------
template<int BM, int BN, int TM, int TN, int NT, bool TRANSB, bool RELU>
__global__ void __launch_bounds__(NT, 2)
gemm_k(const float* __restrict__ A, const float* __restrict__ Bm,
       const float* __restrict__ bias, float* __restrict__ C,
       int K, int lda, int ldb, int ldc, float alpha)
{
    constexpr int TX = BN / TN;
    constexpr int TY = BM / TM;
    constexpr int AREG = BM * 16 / NT;
    constexpr int BREG = BN * 16 / NT;
    static_assert(TX * TY == NT, "thread count mismatch");

    __shared__ float2 As2[2][16][BM + 2];
    __shared__ float  Bs[2][16][BN + 4];

    const int m0 = blockIdx.y * BM;
    const int n0 = blockIdx.x * BN;
    const int t  = threadIdx.x;
    const int tx = t % TX, ty = t / TX;

    float2 acc[TM][TN / 2];
    #pragma unroll
    for (int i = 0; i < TM; i++)
        #pragma unroll
        for (int j = 0; j < TN / 2; j++) acc[i][j] = make_float2(0.f, 0.f);

    float ar[AREG], br[BREG];

    #pragma unroll
    for (int i = 0; i < AREG; i++) {
        int idx = t + i * NT;
        int r = idx >> 4, c = idx & 15;
        ar[i] = A[(long)(m0 + r) * lda + c];
    }
    #pragma unroll
    for (int i = 0; i < BREG; i++) {
        int idx = t + i * NT;
        if (TRANSB) { int r = idx >> 4, c = idx & 15; br[i] = Bm[(long)(n0 + r) * ldb + c]; }
        else        { int kk = idx / BN, nn = idx % BN; br[i] = Bm[(long)kk * ldb + (n0 + nn)]; }
    }
    #pragma unroll
    for (int i = 0; i < AREG; i++) {
        int idx = t + i * NT;
        int r = idx >> 4, c = idx & 15;
        As2[0][c][r] = make_float2(ar[i], ar[i]);
    }
    #pragma unroll
    for (int i = 0; i < BREG; i++) {
        int idx = t + i * NT;
        if (TRANSB) { int r = idx >> 4, c = idx & 15; Bs[0][c][r] = br[i]; }
        else        { int kk = idx / BN, nn = idx % BN; Bs[0][kk][nn] = br[i]; }
    }
    __syncthreads();

    const int nt = K >> 4;
    for (int tt = 0; tt < nt; tt++) {
        const int cur = tt & 1;
        const int k1 = (tt + 1) << 4;
        if (tt + 1 < nt) {
            #pragma unroll
            for (int i = 0; i < AREG; i++) {
                int idx = t + i * NT;
                int r = idx >> 4, c = idx & 15;
                ar[i] = A[(long)(m0 + r) * lda + (k1 + c)];
            }
            #pragma unroll
            for (int i = 0; i < BREG; i++) {
                int idx = t + i * NT;
                if (TRANSB) { int r = idx >> 4, c = idx & 15; br[i] = Bm[(long)(n0 + r) * ldb + (k1 + c)]; }
                else        { int kk = idx / BN, nn = idx % BN; br[i] = Bm[(long)(k1 + kk) * ldb + (n0 + nn)]; }
            }
        }
        #pragma unroll
        for (int kk = 0; kk < 16; kk++) {
            float2 a2[TM], b2[TN / 2];
            #pragma unroll
            for (int i = 0; i < TM; i++) a2[i] = As2[cur][kk][ty * TM + i];
            #pragma unroll
            for (int j = 0; j < TN / 2; j++)
                b2[j] = *(const float2*)&Bs[cur][kk][tx * TN + 2 * j];
            #pragma unroll
            for (int i = 0; i < TM; i++)
                #pragma unroll
                for (int j = 0; j < TN / 2; j++)
                    acc[i][j] = ffma2(a2[i], b2[j], acc[i][j]);
        }
        if (tt + 1 < nt) {
            const int nxt = cur ^ 1;
            #pragma unroll
            for (int i = 0; i < AREG; i++) {
                int idx = t + i * NT;
                int r = idx >> 4, c = idx & 15;
                As2[nxt][c][r] = make_float2(ar[i], ar[i]);
            }
            #pragma unroll
            for (int i = 0; i < BREG; i++) {
                int idx = t + i * NT;
                if (TRANSB) { int r = idx >> 4, c = idx & 15; Bs[nxt][c][r] = br[i]; }
                else        { int kk = idx / BN, nn = idx % BN; Bs[nxt][kk][nn] = br[i]; }
            }
        }
        __syncthreads();
    }

    #pragma unroll
    for (int i = 0; i < TM; i++) {
        float* crow = C + (long)(m0 + ty * TM + i) * ldc + n0 + tx * TN;
        #pragma unroll
        for (int j = 0; j < TN / 2; j++) {
            float2 v = acc[i][j];
            v.x *= alpha; v.y *= alpha;
            if (bias) {
                v.x += bias[n0 + tx * TN + 2 * j];
                v.y += bias[n0 + tx * TN + 2 * j + 1];
            }
            if (RELU) { v.x = fmaxf(v.x, 0.f); v.y = fmaxf(v.y, 0.f); }
            *(float2*)(crow + 2 * j) = v;
        }
    }
}

// ---------------- GEMM v2: 128x128 tile, TM=TN=8, lean smem (1 B/FMA) ----------------
// C = A @ B^T + bias (TRANSB weights), optional relu. 256 threads, double-buffered.
// K % 16 == 0, M % 128 == 0, N % 128 == 0.
template<bool RELU>
__global__ void __launch_bounds__(256, 2)
gemm2_k(const float* __restrict__ A, const float* __restrict__ Bm,
        const float* __restrict__ bias, float* __restrict__ C,
        int K, int lda, int ldb, int ldc)
{
    __shared__ float As[2][16][132];
    __shared__ float Bs[2][16][132];

    const int m0 = blockIdx.y * 128;
    const int n0 = blockIdx.x * 128;
    const int t  = threadIdx.x;
    const int tx = t & 15, ty = t >> 4;

    float2 acc[8][4];
    #pragma unroll
    for (int i = 0; i < 8; i++)
        #pragma unroll
        for (int j = 0; j < 4; j++) acc[i][j] = make_float2(0.f, 0.f);

    float ar[8], br[8];

    // prologue: tile 0  (idx = t + i*256 -> r = idx>>4 (0..127), c = idx&15)
    #pragma unroll
    for (int i = 0; i < 8; i++) {
        int idx = t + i * 256;
        int r = idx >> 4, c = idx & 15;
        ar[i] = A[(long)(m0 + r) * lda + c];
        br[i] = Bm[(long)(n0 + r) * ldb + c];
    }
    #pragma unroll
    for (int i = 0; i < 8; i++) {
        int idx = t + i * 256;
        int r = idx >> 4, c = idx & 15;
        As[0][c][r] = ar[i];
        Bs[0][c][r] = br[i];
    }
    __syncthreads();

    const int nt = K >> 4;
    for (int tt = 0; tt < nt; tt++) {
        const int cur = tt & 1;
        const int k1 = (tt + 1) << 4;
        if (tt + 1 < nt) {
            #pragma unroll
            for (int i = 0; i < 8; i++) {
                int idx = t + i * 256;
                int r = idx >> 4, c = idx & 15;
                ar[i] = A[(long)(m0 + r) * lda + (k1 + c)];
                br[i] = Bm[(long)(n0 + r) * ldb + (k1 + c)];
            }
        }
        #pragma unroll
        for (int kk = 0; kk < 16; kk++) {
            float4 a0 = *(const float4*)&As[cur][kk][ty * 8];
            float4 a1 = *(const float4*)&As[cur][kk][ty * 8 + 4];
            float4 b0 = *(const float4*)&Bs[cur][kk][tx * 8];
            float4 b1 = *(const float4*)&Bs[cur][kk][tx * 8 + 4];
            float2 bv[4];
            bv[0] = make_float2(b0.x, b0.y); bv[1] = make_float2(b0.z, b0.w);
            bv[2] = make_float2(b1.x, b1.y); bv[3] = make_float2(b1.z, b1.w);
            float av[8] = {a0.x, a0.y, a0.z, a0.w, a1.x, a1.y, a1.z, a1.w};
            #pragma unroll
            for (int i = 0; i < 8; i++) {
                float2 a2 = make_float2(av[i], av[i]);
                #pragma unroll
                for (int j = 0; j < 4; j++)
                    acc[i][j] = ffma2(a2, bv[j], acc[i][j]);
            }
        }
        if (tt + 1 < nt) {
            const int nxt = cur ^ 1;
            #pragma unroll
            for (int i = 0; i < 8; i++) {
                int idx = t + i * 256;
                int r = idx >> 4, c = idx & 15;
                As[nxt][c][r] = ar[i];
                Bs[nxt][c][r] = br[i];
            }
        }
        __syncthreads();
    }

    // epilogue
    float bv[8];
    #pragma unroll
    for (int j = 0; j < 8; j++) bv[j] = bias ? bias[n0 + tx * 8 + j] : 0.f;
    #pragma unroll
    for (int i = 0; i < 8; i++) {
        float* crow = C + (long)(m0 + ty * 8 + i) * ldc + n0 + tx * 8;
        float4 o0, o1;
        o0.x = acc[i][0].x + bv[0]; o0.y = acc[i][0].y + bv[1];
        o0.z = acc[i][1].x + bv[2]; o0.w = acc[i][1].y + bv[3];
        o1.x = acc[i][2].x + bv[4]; o1.y = acc[i][2].y + bv[5];
        o1.z = acc[i][3].x + bv[6]; o1.w = acc[i][3].y + bv[7];
        if (RELU) {
            o0.x = fmaxf(o0.x, 0.f); o0.y = fmaxf(o0.y, 0.f);
            o0.z = fmaxf(o0.z, 0.f); o0.w = fmaxf(o0.w, 0.f);
            o1.x = fmaxf(o1.x, 0.f); o1.y = fmaxf(o1.y, 0.f);
            o1.z = fmaxf(o1.z, 0.f); o1.w = fmaxf(o1.w, 0.f);
        }
        *(float4*)crow = o0;
        *(float4*)(crow + 4) = o1;
    }
}

// ---------------- flash attention (fp32, online softmax) ----------------
__global__ void __launch_bounds__(256, 2)
flash_k(const float* __restrict__ qkb, const float* __restrict__ vb,
        float* __restrict__ out)
{
    __shared__ float Qs[64][36];
    __shared__ float Kt[32][68];
    __shared__ float Vs[64][36];
    __shared__ float Ps[64][66];

    const int z = blockIdx.z;
    const int b = z >> 3, h = z & 7;
    const int q0 = blockIdx.x * 64;
    const int t = threadIdx.x;
    const int tx = t & 15, ty = t >> 4;

    const float* Qg = qkb + ((long)(b * 1024 + q0)) * 512 + h * 32;
    const float* Kg = qkb + (long)b * 1024 * 512 + 256 + h * 32;
    const float* Vg = vb + (long)b * 1024 * 256 + h * 32;

    const float scale = 0.1767766952966369f;

    {
        int r = t >> 2, c0 = (t & 3) * 8;
        float4 v0 = *(const float4*)(Qg + (long)r * 512 + c0);
        float4 v1 = *(const float4*)(Qg + (long)r * 512 + c0 + 4);
        v0.x *= scale; v0.y *= scale; v0.z *= scale; v0.w *= scale;
        v1.x *= scale; v1.y *= scale; v1.z *= scale; v1.w *= scale;
        *(float4*)&Qs[r][c0] = v0;
        *(float4*)&Qs[r][c0 + 4] = v1;
    }

    float m[4], l[4];
    float2 o[4];
    #pragma unroll
    for (int i = 0; i < 4; i++) { m[i] = -3.4e38f; l[i] = 0.f; o[i] = make_float2(0.f, 0.f); }

    for (int kv0 = 0; kv0 < 1024; kv0 += 64) {
        {
            int r = t >> 2, c0 = (t & 3) * 8;
            const float* kp = Kg + (long)(kv0 + r) * 512 + c0;
            float4 a = *(const float4*)kp;
            float4 bb = *(const float4*)(kp + 4);
            Kt[c0 + 0][r] = a.x;  Kt[c0 + 1][r] = a.y;
            Kt[c0 + 2][r] = a.z;  Kt[c0 + 3][r] = a.w;
            Kt[c0 + 4][r] = bb.x; Kt[c0 + 5][r] = bb.y;
            Kt[c0 + 6][r] = bb.z; Kt[c0 + 7][r] = bb.w;
            const float* vp = Vg + (long)(kv0 + r) * 256 + c0;
            *(float4*)&Vs[r][c0]     = *(const float4*)vp;
            *(float4*)&Vs[r][c0 + 4] = *(const float4*)(vp + 4);
        }
        __syncthreads();

        float2 acc[4][2];
        #pragma unroll
        for (int i = 0; i < 4; i++) { acc[i][0] = make_float2(0.f, 0.f); acc[i][1] = make_float2(0.f, 0.f); }
        #pragma unroll
        for (int kk = 0; kk < 32; kk++) {
            float4 b4 = *(const float4*)&Kt[kk][tx * 4];
            float2 blo = make_float2(b4.x, b4.y);
            float2 bhi = make_float2(b4.z, b4.w);
            #pragma unroll
            for (int i = 0; i < 4; i++) {
                float a = Qs[ty * 4 + i][kk];
                float2 a2 = make_float2(a, a);
                acc[i][0] = ffma2(a2, blo, acc[i][0]);
                acc[i][1] = ffma2(a2, bhi, acc[i][1]);
            }
        }

        #pragma unroll
        for (int i = 0; i < 4; i++) {
            float s0 = acc[i][0].x, s1 = acc[i][0].y, s2 = acc[i][1].x, s3 = acc[i][1].y;
            float mx = fmaxf(fmaxf(s0, s1), fmaxf(s2, s3));
            #pragma unroll
            for (int off = 1; off < 16; off <<= 1)
                mx = fmaxf(mx, __shfl_xor_sync(0xffffffffu, mx, off));
            float mnew = fmaxf(m[i], mx);
            float p0 = __expf(s0 - mnew), p1 = __expf(s1 - mnew);
            float p2 = __expf(s2 - mnew), p3 = __expf(s3 - mnew);
            float rs = p0 + p1 + p2 + p3;
            #pragma unroll
            for (int off = 1; off < 16; off <<= 1)
                rs += __shfl_xor_sync(0xffffffffu, rs, off);
            float sc_ = __expf(m[i] - mnew);
            l[i] = l[i] * sc_ + rs;
            o[i].x *= sc_; o[i].y *= sc_;
            m[i] = mnew;
            float* pr = &Ps[ty * 4 + i][tx * 4];
            pr[0] = p0; pr[1] = p1; pr[2] = p2; pr[3] = p3;
        }
        __syncthreads();

        #pragma unroll 4
        for (int kv = 0; kv < 64; kv++) {
            float2 v2 = *(const float2*)&Vs[kv][tx * 2];
            #pragma unroll
            for (int i = 0; i < 4; i++) {
                float p = Ps[ty * 4 + i][kv];
                o[i] = ffma2(make_float2(p, p), v2, o[i]);
            }
        }
        __syncthreads();
    }

    #pragma unroll
    for (int i = 0; i < 4; i++) {
        float inv = 1.f / l[i];
        float2 r = make_float2(o[i].x * inv, o[i].y * inv);
        *(float2*)(out + ((long)(b * 1024 + q0 + ty * 4 + i)) * 256 + h * 32 + tx * 2) = r;
    }
}

// ---------------- residual + layernorm ----------------
__global__ void resln_k(const float* __restrict__ a, const float* __restrict__ b,
                        const float* __restrict__ g, const float* __restrict__ be,
                        float* __restrict__ out,
                        const float* __restrict__ pos, float* __restrict__ out2)
{
    __shared__ float sm[8];
    int row = blockIdx.x, t = threadIdx.x;
    long off = (long)row * NC + t;
    float x = a[off] + b[off];
    float mn = blockSum256(x, sm) * (1.f / NC);
    float d = x - mn;
    float v = blockSum256(d * d, sm) * (1.f / NC);
    float y = d * rsqrtf(v + 1e-5f) * g[t] + be[t];
    out[off] = y;
    if (out2) out2[off] = y + pos[off];
}

// ---------------- deformable sampling ----------------
__global__ void deform_k(const float* __restrict__ value,
                         const float* __restrict__ offaw,
                         const float* __restrict__ refp,
                         float* __restrict__ out)
{
    int gw   = (blockIdx.x * blockDim.x + threadIdx.x) >> 5;
    int lane = threadIdx.x & 31;
    int h  = gw & 7;
    int bq = gw >> 3;
    int b  = bq >> 10;

    const float* ap = offaw + (long)bq * 384 + 256 + h * 16;
    float w[16];
    float mx = -3.4e38f;
    #pragma unroll
    for (int j = 0; j < 16; j++) { w[j] = ap[j]; mx = fmaxf(mx, w[j]); }
    float s = 0.f;
    #pragma unroll
    for (int j = 0; j < 16; j++) { w[j] = __expf(w[j] - mx); s += w[j]; }
    float inv = 1.f / s;

    const float* op = offaw + (long)bq * 384 + h * 32;
    const float* rp = refp + (long)bq * 8;
    const float* vb = value + (long)b * NLSRC * NC + h * NDH + lane;

    const int wl_[4] = {128, 64, 32, 16};
    const int st_[4] = {0, 16384, 20480, 21504};

    float acc = 0.f;
    #pragma unroll
    for (int l = 0; l < 4; l++) {
        const int W = wl_[l], Hh = wl_[l];
        const int st = st_[l];
        float rx = rp[l * 2 + 0] * (float)W  - 0.5f;
        float ry = rp[l * 2 + 1] * (float)Hh - 0.5f;
        #pragma unroll
        for (int p = 0; p < 4; p++) {
            float a = w[l * 4 + p] * inv;
            float x = rx + op[(l * 4 + p) * 2 + 0];
            float y = ry + op[(l * 4 + p) * 2 + 1];
            float xf = floorf(x), yf = floorf(y);
            int x0 = (int)xf, y0 = (int)yf;
            float wx1 = x - xf, wy1 = y - yf;
            float wx0 = 1.f - wx1, wy0 = 1.f - wy1;
            #pragma unroll
            for (int cy = 0; cy < 2; cy++) {
                int iy = y0 + cy;
                if (iy < 0 || iy >= Hh) continue;
                float wy = cy ? wy1 : wy0;
                #pragma unroll
                for (int cx = 0; cx < 2; cx++) {
                    int ix = x0 + cx;
                    if (ix < 0 || ix >= W) continue;
                    float cw = a * wy * (cx ? wx1 : wx0);
                    acc += cw * vb[(long)(st + iy * W + ix) * NC];
                }
            }
        }
    }
    out[(long)bq * NC + h * NDH + lane] = acc;
}

extern "C" void kernel_launch(void* const* d_in, const int* in_sizes, int n_in,
                              void* d_out, int out_size)
{
    const float* tgt   = (const float*)d_in[0];
    const float* qpos  = (const float*)d_in[1];
    const float* refp  = (const float*)d_in[2];
    const float* src   = (const float*)d_in[3];
    const float* in_w  = (const float*)d_in[4];
    const float* in_b  = (const float*)d_in[5];
    const float* sa_w  = (const float*)d_in[6];
    const float* sa_b  = (const float*)d_in[7];
    const float* off_w = (const float*)d_in[8];
    const float* off_b = (const float*)d_in[9];
    const float* aw_w  = (const float*)d_in[10];
    const float* aw_b  = (const float*)d_in[11];
    const float* val_w = (const float*)d_in[12];
    const float* val_b = (const float*)d_in[13];
    const float* co_w  = (const float*)d_in[14];
    const float* co_b  = (const float*)d_in[15];
    const float* ln1_g = (const float*)d_in[16];
    const float* ln1_b = (const float*)d_in[17];
    const float* ln2_g = (const float*)d_in[18];
    const float* ln2_b = (const float*)d_in[19];
    const float* ln3_g = (const float*)d_in[20];
    const float* ln3_b = (const float*)d_in[21];
    const float* f1_w  = (const float*)d_in[22];
    const float* f1_b  = (const float*)d_in[23];
    const float* f2_w  = (const float*)d_in[24];
    const float* f2_b  = (const float*)d_in[25];

    float* S = nullptr;
    cudaGetSymbolAddress((void**)&S, g_scratch);

    float* qk    = S + OFF_QK;
    float* qkb   = S + OFF_QKB;
    float* vb    = S + OFF_V;
    float* att   = S + OFF_ATT;
    float* tmp   = S + OFF_TMP;
    float* tgt1  = S + OFF_TGT1;
    float* xq    = S + OFF_X;
    float* offaw = S + OFF_OFFAW;
    float* samp  = S + OFF_SAMP;
    float* tgt2  = S + OFF_TGT2;
    float* ffn1  = S + OFF_FFN1;
    float* wcat  = S + OFF_WCAT;
    float* valb  = S + OFF_VAL;

    // ---- self-attention ----
    add_k<<<4096, 256>>>(tgt, qpos, qk, NB * NLQ * NC);
    wcat_k<<<(384 * 256 + 384 + 255) / 256, 256>>>(off_w, aw_w, off_b, aw_b, wcat);

    // fused q|k projection: M=4096, N=512, K=256
    gemm_k<128,64,8,4,256,true,false><<<dim3(8,32,1), 256>>>(
        qk, in_w, in_b, qkb, 256, 256, 256, 512, 1.f);
    // v projection: M=4096, N=256
    gemm_k<128,64,8,4,256,true,false><<<dim3(4,32,1), 256>>>(
        tgt, in_w + 131072, in_b + 512, vb, 256, 256, 256, 256, 1.f);

    // fused attention (scores + softmax + PV)
    flash_k<<<dim3(16,1,32), 256>>>(qkb, vb, att);

    // out projection + residual + LN2 (also x = ln_out + pos)
    gemm_k<128,64,8,4,256,true,false><<<dim3(4,32,1), 256>>>(
        att, sa_w, sa_b, tmp, 256, 256, 256, 256, 1.f);
    resln_k<<<4096, 256>>>(tgt, tmp, ln2_g, ln2_b, tgt1, qpos, xq);

    // ---- deformable cross-attention ----
    // value = src @ val_w^T + val_b  (M=87040, N=256): big-tile gemm2
    gemm2_k<false><<<dim3(2, 680, 1), 256>>>(
        src, val_w, val_b, valb, 256, 256, 256, 256);
    // fused offsets + aw logits: N=384
    gemm_k<128,64,8,4,256,true,false><<<dim3(6,32,1), 256>>>(
        xq, wcat, wcat + 384 * 256, offaw, 256, 256, 256, 384, 1.f);

    deform_k<<<4096, 256>>>(valb, offaw, refp, samp);

    gemm_k<128,64,8,4,256,true,false><<<dim3(4,32,1), 256>>>(
        samp, co_w, co_b, tmp, 256, 256, 256, 256, 1.f);
    resln_k<<<4096, 256>>>(tgt1, tmp, ln1_g, ln1_b, tgt2, nullptr, nullptr);

    // ---- FFN ----
    gemm2_k<true><<<dim3(8, 32, 1), 256>>>(
        tgt2, f1_w, f1_b, ffn1, 256, 256, 256, 1024);
    gemm_k<128,64,8,4,256,true,false><<<dim3(4,32,1), 256>>>(
        ffn1, f2_w, f2_b, tmp, 1024, 1024, 1024, 256, 1.f);
    resln_k<<<4096, 256>>>(tgt2, tmp, ln3_g, ln3_b, (float*)d_out, nullptr, nullptr);
}

// round 8
// speedup vs baseline: 1.1845x; 1.0048x over previous
#include <cuda_runtime.h>
#include <math.h>

// Problem constants
#define NB    4
#define NLQ   1024
#define NC    256
#define NH    8
#define NDH   32
#define NDFF  1024
#define NLSRC 21760

// Scratch layout (floats)
#define OFF_QK    0ll
#define OFF_QKB   1048576ll     // [4096,512] q|k
#define OFF_VBW   3145728ll     // [4096,512] v in cols 0..255 (ld 512)
#define OFF_ATT   5242880ll
#define OFF_TMP   6291456ll
#define OFF_TMP2  7340032ll
#define OFF_TGT1  8388608ll
#define OFF_X     9437184ll
#define OFF_OFFAW 10485760ll    // [4096,384]
#define OFF_SAMP  12058624ll
#define OFF_TGT2  13107200ll
#define OFF_FFN1  14155776ll    // 4M
#define OFF_WCAT  18350080ll    // 384*256+384
#define OFF_VAL   18481152ll    // 22282240
#define SCRATCH_TOTAL (OFF_VAL + 22282240ll)

__device__ float g_scratch[SCRATCH_TOTAL];

// ---------------- packed fp32x2 FMA (Blackwell FFMA2) ----------------
union U64f2 { float2 f2; unsigned long long u; };
__device__ __forceinline__ float2 ffma2(float2 a, float2 b, float2 c) {
    U64f2 A, B, C, D;
    A.f2 = a; B.f2 = b; C.f2 = c;
    asm("fma.rn.f32x2 %0, %1, %2, %3;" : "=l"(D.u) : "l"(A.u), "l"(B.u), "l"(C.u));
    return D.f2;
}

// ---------------- elementwise add ----------------
__global__ void add_k(const float* __restrict__ a, const float* __restrict__ b,
                      float* __restrict__ o, int n) {
    int i = blockIdx.x * blockDim.x + threadIdx.x;
    if (i < n) o[i] = a[i] + b[i];
}

// ---------------- weight concat (off_w | aw_w) + biases ----------------
__global__ void wcat_k(const float* __restrict__ off_w, const float* __restrict__ aw_w,
                       const float* __restrict__ off_b, const float* __restrict__ aw_b,
                       float* __restrict__ wcat) {
    int i = blockIdx.x * blockDim.x + threadIdx.x;
    if (i < 384 * 256) {
        int row = i >> 8, col = i & 255;
        wcat[i] = (row < 256) ? off_w[row * 256 + col] : aw_w[(row - 256) * 256 + col];
    } else if (i < 384 * 256 + 384) {
        int j = i - 384 * 256;
        wcat[i] = (j < 256) ? off_b[j] : aw_b[j - 256];
    }
}

// ---------------- block reduce helper (256 threads) ----------------
__device__ __forceinline__ float blockSum256(float v, float* sm) {
    #pragma unroll
    for (int o = 16; o > 0; o >>= 1) v += __shfl_xor_sync(0xffffffffu, v, o);
    __syncthreads();
    if ((threadIdx.x & 31) == 0) sm[threadIdx.x >> 5] = v;
    __syncthreads();
    return sm[0] + sm[1] + sm[2] + sm[3] + sm[4] + sm[5] + sm[6] + sm[7];
}

// ---------------- GEMM v1: duplicated-A f32x2, z-batched ----------------
// C = A @ B^T + bias (weights [N,K] row-major). z -> (zo=z/zdiv, zi=z%zdiv).
template<int BM, int BN, int TM, int TN, int NT, bool RELU>
__global__ void __launch_bounds__(NT, 2)
gemm_k(const float* __restrict__ A, const float* __restrict__ Bm,
       const float* __restrict__ bias, float* __restrict__ C,
       int K, int lda, int ldb, int ldc,
       int zdiv, long sA0, long sB0, long sB1, long sC0, long sC1,
       long sb0, long sb1)
{
    constexpr int TX = BN / TN;
    constexpr int TY = BM / TM;
    constexpr int AREG = BM * 16 / NT;
    constexpr int BREG = BN * 16 / NT;
    static_assert(TX * TY == NT, "thread count mismatch");

    __shared__ float2 As2[2][16][BM + 2];
    __shared__ float  Bs[2][16][BN + 4];

    const int z = blockIdx.z;
    const long zo = z / zdiv, zi = z % zdiv;
    A  += zo * sA0;
    Bm += zo * sB0 + zi * sB1;
    C  += zo * sC0 + zi * sC1;
    if (bias) bias += zo * sb0 + zi * sb1;

    const int m0 = blockIdx.y * BM;
    const int n0 = blockIdx.x * BN;
    const int t  = threadIdx.x;
    const int tx = t % TX, ty = t / TX;

    float2 acc[TM][TN / 2];
    #pragma unroll
    for (int i = 0; i < TM; i++)
        #pragma unroll
        for (int j = 0; j < TN / 2; j++) acc[i][j] = make_float2(0.f, 0.f);

    float ar[AREG], br[BREG];

    #pragma unroll
    for (int i = 0; i < AREG; i++) {
        int idx = t + i * NT;
        int r = idx >> 4, c = idx & 15;
        ar[i] = A[(long)(m0 + r) * lda + c];
    }
    #pragma unroll
    for (int i = 0; i < BREG; i++) {
        int idx = t + i * NT;
        int r = idx >> 4, c = idx & 15;
        br[i] = Bm[(long)(n0 + r) * ldb + c];
    }
    #pragma unroll
    for (int i = 0; i < AREG; i++) {
        int idx = t + i * NT;
        int r = idx >> 4, c = idx & 15;
        As2[0][c][r] = make_float2(ar[i], ar[i]);
    }
    #pragma unroll
    for (int i = 0; i < BREG; i++) {
        int idx = t + i * NT;
        int r = idx >> 4, c = idx & 15;
        Bs[0][c][r] = br[i];
    }
    __syncthreads();

    const int nt = K >> 4;
    for (int tt = 0; tt < nt; tt++) {
        const int cur = tt & 1;
        const int k1 = (tt + 1) << 4;
        if (tt + 1 < nt) {
            #pragma unroll
            for (int i = 0; i < AREG; i++) {
                int idx = t + i * NT;
                int r = idx >> 4, c = idx & 15;
                ar[i] = A[(long)(m0 + r) * lda + (k1 + c)];
            }
            #pragma unroll
            for (int i = 0; i < BREG; i++) {
                int idx = t + i * NT;
                int r = idx >> 4, c = idx & 15;
                br[i] = Bm[(long)(n0 + r) * ldb + (k1 + c)];
            }
        }
        #pragma unroll
        for (int kk = 0; kk < 16; kk++) {
            float2 a2[TM], b2[TN / 2];
            #pragma unroll
            for (int i = 0; i < TM; i++) a2[i] = As2[cur][kk][ty * TM + i];
            #pragma unroll
            for (int j = 0; j < TN / 2; j++)
                b2[j] = *(const float2*)&Bs[cur][kk][tx * TN + 2 * j];
            #pragma unroll
            for (int i = 0; i < TM; i++)
                #pragma unroll
                for (int j = 0; j < TN / 2; j++)
                    acc[i][j] = ffma2(a2[i], b2[j], acc[i][j]);
        }
        if (tt + 1 < nt) {
            const int nxt = cur ^ 1;
            #pragma unroll
            for (int i = 0; i < AREG; i++) {
                int idx = t + i * NT;
                int r = idx >> 4, c = idx & 15;
                As2[nxt][c][r] = make_float2(ar[i], ar[i]);
            }
            #pragma unroll
            for (int i = 0; i < BREG; i++) {
                int idx = t + i * NT;
                int r = idx >> 4, c = idx & 15;
                Bs[nxt][c][r] = br[i];
            }
        }
        __syncthreads();
    }

    #pragma unroll
    for (int i = 0; i < TM; i++) {
        float* crow = C + (long)(m0 + ty * TM + i) * ldc + n0 + tx * TN;
        #pragma unroll
        for (int j = 0; j < TN / 2; j++) {
            float2 v = acc[i][j];
            if (bias) {
                v.x += bias[n0 + tx * TN + 2 * j];
                v.y += bias[n0 + tx * TN + 2 * j + 1];
            }
            if (RELU) { v.x = fmaxf(v.x, 0.f); v.y = fmaxf(v.y, 0.f); }
            *(float2*)(crow + 2 * j) = v;
        }
    }
}

// ---------------- GEMM v2: 128x128 tile, TM=TN=8, lean smem ----------------
template<bool RELU>
__global__ void __launch_bounds__(256, 2)
gemm2_k(const float* __restrict__ A, const float* __restrict__ Bm,
        const float* __restrict__ bias, float* __restrict__ C,
        int K, int lda, int ldb, int ldc)
{
    __shared__ float As[2][16][132];
    __shared__ float Bs[2][16][132];

    const int m0 = blockIdx.y * 128;
    const int n0 = blockIdx.x * 128;
    const int t  = threadIdx.x;
    const int tx = t & 15, ty = t >> 4;

    float2 acc[8][4];
    #pragma unroll
    for (int i = 0; i < 8; i++)
        #pragma unroll
        for (int j = 0; j < 4; j++) acc[i][j] = make_float2(0.f, 0.f);

    float ar[8], br[8];

    #pragma unroll
    for (int i = 0; i < 8; i++) {
        int idx = t + i * 256;
        int r = idx >> 4, c = idx & 15;
        ar[i] = A[(long)(m0 + r) * lda + c];
        br[i] = Bm[(long)(n0 + r) * ldb + c];
    }
    #pragma unroll
    for (int i = 0; i < 8; i++) {
        int idx = t + i * 256;
        int r = idx >> 4, c = idx & 15;
        As[0][c][r] = ar[i];
        Bs[0][c][r] = br[i];
    }
    __syncthreads();

    const int nt = K >> 4;
    for (int tt = 0; tt < nt; tt++) {
        const int cur = tt & 1;
        const int k1 = (tt + 1) << 4;
        if (tt + 1 < nt) {
            #pragma unroll
            for (int i = 0; i < 8; i++) {
                int idx = t + i * 256;
                int r = idx >> 4, c = idx & 15;
                ar[i] = A[(long)(m0 + r) * lda + (k1 + c)];
                br[i] = Bm[(long)(n0 + r) * ldb + (k1 + c)];
            }
        }
        #pragma unroll
        for (int kk = 0; kk < 16; kk++) {
            float4 a0 = *(const float4*)&As[cur][kk][ty * 8];
            float4 a1 = *(const float4*)&As[cur][kk][ty * 8 + 4];
            float4 b0 = *(const float4*)&Bs[cur][kk][tx * 8];
            float4 b1 = *(const float4*)&Bs[cur][kk][tx * 8 + 4];
            float2 bv[4];
            bv[0] = make_float2(b0.x, b0.y); bv[1] = make_float2(b0.z, b0.w);
            bv[2] = make_float2(b1.x, b1.y); bv[3] = make_float2(b1.z, b1.w);
            float av[8] = {a0.x, a0.y, a0.z, a0.w, a1.x, a1.y, a1.z, a1.w};
            #pragma unroll
            for (int i = 0; i < 8; i++) {
                float2 a2 = make_float2(av[i], av[i]);
                #pragma unroll
                for (int j = 0; j < 4; j++)
                    acc[i][j] = ffma2(a2, bv[j], acc[i][j]);
            }
        }
        if (tt + 1 < nt) {
            const int nxt = cur ^ 1;
            #pragma unroll
            for (int i = 0; i < 8; i++) {
                int idx = t + i * 256;
                int r = idx >> 4, c = idx & 15;
                As[nxt][c][r] = ar[i];
                Bs[nxt][c][r] = br[i];
            }
        }
        __syncthreads();
    }

    float bv[8];
    #pragma unroll
    for (int j = 0; j < 8; j++) bv[j] = bias ? bias[n0 + tx * 8 + j] : 0.f;
    #pragma unroll
    for (int i = 0; i < 8; i++) {
        float* crow = C + (long)(m0 + ty * 8 + i) * ldc + n0 + tx * 8;
        float4 o0, o1;
        o0.x = acc[i][0].x + bv[0]; o0.y = acc[i][0].y + bv[1];
        o0.z = acc[i][1].x + bv[2]; o0.w = acc[i][1].y + bv[3];
        o1.x = acc[i][2].x + bv[4]; o1.y = acc[i][2].y + bv[5];
        o1.z = acc[i][3].x + bv[6]; o1.w = acc[i][3].y + bv[7];
        if (RELU) {
            o0.x = fmaxf(o0.x, 0.f); o0.y = fmaxf(o0.y, 0.f);
            o0.z = fmaxf(o0.z, 0.f); o0.w = fmaxf(o0.w, 0.f);
            o1.x = fmaxf(o1.x, 0.f); o1.y = fmaxf(o1.y, 0.f);
            o1.z = fmaxf(o1.z, 0.f); o1.w = fmaxf(o1.w, 0.f);
        }
        *(float4*)crow = o0;
        *(float4*)(crow + 4) = o1;
    }
}

// ---------------- flash attention (fp32, online softmax) ----------------
// Q and K from qkb [4096,512] (q at h*32, k at 256+h*32); V from vbw [4096,512] cols 0..255.
__global__ void __launch_bounds__(256, 2)
flash_k(const float* __restrict__ qkb, const float* __restrict__ vbw,
        float* __restrict__ out)
{
    __shared__ float Qt[32][68];   // [dh][q]  (transposed)
    __shared__ float Kt[32][68];   // [dh][kv]
    __shared__ float Vs[64][36];
    __shared__ float Ps[64][68];   // padded 68 for 16B-aligned float4 rows

    const int z = blockIdx.z;
    const int b = z >> 3, h = z & 7;
    const int q0 = blockIdx.x * 64;
    const int t = threadIdx.x;
    const int tx = t & 15, ty = t >> 4;

    const float* Qg = qkb + ((long)(b * 1024 + q0)) * 512 + h * 32;
    const float* Kg = qkb + (long)b * 1024 * 512 + 256 + h * 32;
    const float* Vg = vbw + (long)b * 1024 * 512 + h * 32;

    const float scale = 0.1767766952966369f;

    // load Q tile transposed (scaled)
    {
        int r = t >> 2, c0 = (t & 3) * 8;
        float4 v0 = *(const float4*)(Qg + (long)r * 512 + c0);
        float4 v1 = *(const float4*)(Qg + (long)r * 512 + c0 + 4);
        Qt[c0 + 0][r] = v0.x * scale; Qt[c0 + 1][r] = v0.y * scale;
        Qt[c0 + 2][r] = v0.z * scale; Qt[c0 + 3][r] = v0.w * scale;
        Qt[c0 + 4][r] = v1.x * scale; Qt[c0 + 5][r] = v1.y * scale;
        Qt[c0 + 6][r] = v1.z * scale; Qt[c0 + 7][r] = v1.w * scale;
    }

    float m[4], l[4];
    float2 o[4];
    #pragma unroll
    for (int i = 0; i < 4; i++) { m[i] = -3.4e38f; l[i] = 0.f; o[i] = make_float2(0.f, 0.f); }

    for (int kv0 = 0; kv0 < 1024; kv0 += 64) {
        {
            int r = t >> 2, c0 = (t & 3) * 8;
            const float* kp = Kg + (long)(kv0 + r) * 512 + c0;
            float4 a = *(const float4*)kp;
            float4 bb = *(const float4*)(kp + 4);
            Kt[c0 + 0][r] = a.x;  Kt[c0 + 1][r] = a.y;
            Kt[c0 + 2][r] = a.z;  Kt[c0 + 3][r] = a.w;
            Kt[c0 + 4][r] = bb.x; Kt[c0 + 5][r] = bb.y;
            Kt[c0 + 6][r] = bb.z; Kt[c0 + 7][r] = bb.w;
            const float* vp = Vg + (long)(kv0 + r) * 512 + c0;
            *(float4*)&Vs[r][c0]     = *(const float4*)vp;
            *(float4*)&Vs[r][c0 + 4] = *(const float4*)(vp + 4);
        }
        __syncthreads();

        // S tile: 4q x 4kv per thread — 2 LDS.128 + 8 FFMA2 per k
        float2 acc[4][2];
        #pragma unroll
        for (int i = 0; i < 4; i++) { acc[i][0] = make_float2(0.f, 0.f); acc[i][1] = make_float2(0.f, 0.f); }
        #pragma unroll
        for (int kk = 0; kk < 32; kk++) {
            float4 q4 = *(const float4*)&Qt[kk][ty * 4];
            float4 k4 = *(const float4*)&Kt[kk][tx * 4];
            float2 blo = make_float2(k4.x, k4.y);
            float2 bhi = make_float2(k4.z, k4.w);
            float qa[4] = {q4.x, q4.y, q4.z, q4.w};
            #pragma unroll
            for (int i = 0; i < 4; i++) {
                float2 a2 = make_float2(qa[i], qa[i]);
                acc[i][0] = ffma2(a2, blo, acc[i][0]);
                acc[i][1] = ffma2(a2, bhi, acc[i][1]);
            }
        }

        // online softmax update per q row
        #pragma unroll
        for (int i = 0; i < 4; i++) {
            float s0 = acc[i][0].x, s1 = acc[i][0].y, s2 = acc[i][1].x, s3 = acc[i][1].y;
            float mx = fmaxf(fmaxf(s0, s1), fmaxf(s2, s3));
            #pragma unroll
            for (int off = 1; off < 16; off <<= 1)
                mx = fmaxf(mx, __shfl_xor_sync(0xffffffffu, mx, off));
            float mnew = fmaxf(m[i], mx);
            float p0 = __expf(s0 - mnew), p1 = __expf(s1 - mnew);
            float p2 = __expf(s2 - mnew), p3 = __expf(s3 - mnew);
            float rs = p0 + p1 + p2 + p3;
            #pragma unroll
            for (int off = 1; off < 16; off <<= 1)
                rs += __shfl_xor_sync(0xffffffffu, rs, off);
            float sc_ = __expf(m[i] - mnew);
            l[i] = l[i] * sc_ + rs;
            o[i].x *= sc_; o[i].y *= sc_;
            m[i] = mnew;
            float4 pv = make_float4(p0, p1, p2, p3);
            *(float4*)&Ps[ty * 4 + i][tx * 4] = pv;
        }
        __syncthreads();

        // O += P @ V  — unrolled x4, float4 P loads
        #pragma unroll
        for (int kv = 0; kv < 64; kv += 4) {
            float2 v0 = *(const float2*)&Vs[kv + 0][tx * 2];
            float2 v1 = *(const float2*)&Vs[kv + 1][tx * 2];
            float2 v2 = *(const float2*)&Vs[kv + 2][tx * 2];
            float2 v3 = *(const float2*)&Vs[kv + 3][tx * 2];
            #pragma unroll
            for (int i = 0; i < 4; i++) {
                float4 p = *(const float4*)&Ps[ty * 4 + i][kv];
                o[i] = ffma2(make_float2(p.x, p.x), v0, o[i]);
                o[i] = ffma2(make_float2(p.y, p.y), v1, o[i]);
                o[i] = ffma2(make_float2(p.z, p.z), v2, o[i]);
                o[i] = ffma2(make_float2(p.w, p.w), v3, o[i]);
            }
        }
        __syncthreads();
    }

    #pragma unroll
    for (int i = 0; i < 4; i++) {
        float inv = 1.f / l[i];
        float2 r = make_float2(o[i].x * inv, o[i].y * inv);
        *(float2*)(out + ((long)(b * 1024 + q0 + ty * 4 + i)) * 256 + h * 32 + tx * 2) = r;
    }
}

// ---------------- residual + layernorm (general) ----------------
// x = a + b (+ c) (+ cb[col]); out = LN(x); out2 = out + pos (optional)
__global__ void resln_k(const float* __restrict__ a, const float* __restrict__ b,
                        const float* __restrict__ c, const float* __restrict__ cb,
                        const float* __restrict__ g, const float* __restrict__ be,
                        float* __restrict__ out,
                        const float* __restrict__ pos, float* __restrict__ out2)
{
    __shared__ float sm[8];
    int row = blockIdx.x, t = threadIdx.x;
    long off = (long)row * NC + t;
    float x = a[off] + b[off];
    if (c)  x += c[off];
    if (cb) x += cb[t];
    float mn = blockSum256(x, sm) * (1.f / NC);
    float d = x - mn;
    float v = blockSum256(d * d, sm) * (1.f / NC);
    float y = d * rsqrtf(v + 1e-5f) * g[t] + be[t];
    out[off] = y;
    if (out2) out2[off] = y + pos[off];
}

// ---------------- deformable sampling ----------------
__global__ void deform_k(const float* __restrict__ value,
                         const float* __restrict__ offaw,
                         const float* __restrict__ refp,
                         float* __restrict__ out)
{
    int gw   = (blockIdx.x * blockDim.x + threadIdx.x) >> 5;
    int lane = threadIdx.x & 31;
    int h  = gw & 7;
    int bq = gw >> 3;
    int b  = bq >> 10;

    const float* ap = offaw + (long)bq * 384 + 256 + h * 16;
    float w[16];
    float mx = -3.4e38f;
    #pragma unroll
    for (int j = 0; j < 16; j++) { w[j] = ap[j]; mx = fmaxf(mx, w[j]); }
    float s = 0.f;
    #pragma unroll
    for (int j = 0; j < 16; j++) { w[j] = __expf(w[j] - mx); s += w[j]; }
    float inv = 1.f / s;

    const float* op = offaw + (long)bq * 384 + h * 32;
    const float* rp = refp + (long)bq * 8;
    const float* vb = value + (long)b * NLSRC * NC + h * NDH + lane;

    const int wl_[4] = {128, 64, 32, 16};
    const int st_[4] = {0, 16384, 20480, 21504};

    float acc = 0.f;
    #pragma unroll
    for (int l = 0; l < 4; l++) {
        const int W = wl_[l], Hh = wl_[l];
        const int st = st_[l];
        float rx = rp[l * 2 + 0] * (float)W  - 0.5f;
        float ry = rp[l * 2 + 1] * (float)Hh - 0.5f;
        #pragma unroll
        for (int p = 0; p < 4; p++) {
            float a = w[l * 4 + p] * inv;
            float x = rx + op[(l * 4 + p) * 2 + 0];
            float y = ry + op[(l * 4 + p) * 2 + 1];
            float xf = floorf(x), yf = floorf(y);
            int x0 = (int)xf, y0 = (int)yf;
            float wx1 = x - xf, wy1 = y - yf;
            float wx0 = 1.f - wx1, wy0 = 1.f - wy1;
            #pragma unroll
            for (int cy = 0; cy < 2; cy++) {
                int iy = y0 + cy;
                if (iy < 0 || iy >= Hh) continue;
                float wy = cy ? wy1 : wy0;
                #pragma unroll
                for (int cx = 0; cx < 2; cx++) {
                    int ix = x0 + cx;
                    if (ix < 0 || ix >= W) continue;
                    float cw = a * wy * (cx ? wx1 : wx0);
                    acc += cw * vb[(long)(st + iy * W + ix) * NC];
                }
            }
        }
    }
    out[(long)bq * NC + h * NDH + lane] = acc;
}

extern "C" void kernel_launch(void* const* d_in, const int* in_sizes, int n_in,
                              void* d_out, int out_size)
{
    const float* tgt   = (const float*)d_in[0];
    const float* qpos  = (const float*)d_in[1];
    const float* refp  = (const float*)d_in[2];
    const float* src   = (const float*)d_in[3];
    const float* in_w  = (const float*)d_in[4];
    const float* in_b  = (const float*)d_in[5];
    const float* sa_w  = (const float*)d_in[6];
    const float* sa_b  = (const float*)d_in[7];
    const float* off_w = (const float*)d_in[8];
    const float* off_b = (const float*)d_in[9];
    const float* aw_w  = (const float*)d_in[10];
    const float* aw_b  = (const float*)d_in[11];
    const float* val_w = (const float*)d_in[12];
    const float* val_b = (const float*)d_in[13];
    const float* co_w  = (const float*)d_in[14];
    const float* co_b  = (const float*)d_in[15];
    const float* ln1_g = (const float*)d_in[16];
    const float* ln1_b = (const float*)d_in[17];
    const float* ln2_g = (const float*)d_in[18];
    const float* ln2_b = (const float*)d_in[19];
    const float* ln3_g = (const float*)d_in[20];
    const float* ln3_b = (const float*)d_in[21];
    const float* f1_w  = (const float*)d_in[22];
    const float* f1_b  = (const float*)d_in[23];
    const float* f2_w  = (const float*)d_in[24];
    const float* f2_b  = (const float*)d_in[25];

    float* S = nullptr;
    cudaGetSymbolAddress((void**)&S, g_scratch);

    float* qk    = S + OFF_QK;
    float* qkb   = S + OFF_QKB;
    float* vbw   = S + OFF_VBW;
    float* att   = S + OFF_ATT;
    float* tmp   = S + OFF_TMP;
    float* tmp2  = S + OFF_TMP2;
    float* tgt1  = S + OFF_TGT1;
    float* xq    = S + OFF_X;
    float* offaw = S + OFF_OFFAW;
    float* samp  = S + OFF_SAMP;
    float* tgt2  = S + OFF_TGT2;
    float* ffn1  = S + OFF_FFN1;
    float* wcat  = S + OFF_WCAT;
    float* valb  = S + OFF_VAL;

    // ---- self-attention ----
    add_k<<<4096, 256>>>(tgt, qpos, qk, NB * NLQ * NC);
    wcat_k<<<(384 * 256 + 384 + 255) / 256, 256>>>(off_w, aw_w, off_b, aw_b, wcat);

    // merged q|k|v projection: one launch, z in {0:q, 1:k, 2:v}, zdiv=2
    // zo=z/2 selects A (qk vs tgt) and high B/C offsets; zi=z%2 selects k slice.
    gemm_k<128,64,8,4,256,false><<<dim3(4, 32, 3), 256>>>(
        qk, in_w, in_b, qkb, 256, 256, 256, 512,
        2,
        (long)(tgt - qk),            // sA0
        131072, 65536,               // sB0, sB1
        (long)(vbw - qkb), 256,      // sC0, sC1
        512, 256);                   // bias strides

    // fused attention (scores + softmax + PV)
    flash_k<<<dim3(16, 1, 32), 256>>>(qkb, vbw, att);

    // out projection (128x32 tiles -> 256 blocks) + residual + LN2
    gemm_k<128,32,4,4,256,false><<<dim3(8, 32, 1), 256>>>(
        att, sa_w, sa_b, tmp, 256, 256, 256, 256, 1, 0, 0, 0, 0, 0, 0, 0);
    resln_k<<<4096, 256>>>(tgt, tmp, nullptr, nullptr, ln2_g, ln2_b, tgt1, qpos, xq);

    // ---- deformable cross-attention ----
    gemm2_k<false><<<dim3(2, 680, 1), 256>>>(
        src, val_w, val_b, valb, 256, 256, 256, 256);
    // fused offsets + aw logits: N=384, 128x32 tiles -> 384 blocks
    gemm_k<128,32,4,4,256,false><<<dim3(12, 32, 1), 256>>>(
        xq, wcat, wcat + 384 * 256, offaw, 256, 256, 256, 384, 1, 0, 0, 0, 0, 0, 0, 0);

    deform_k<<<4096, 256>>>(valb, offaw, refp, samp);

    gemm_k<128,32,4,4,256,false><<<dim3(8, 32, 1), 256>>>(
        samp, co_w, co_b, tmp, 256, 256, 256, 256, 1, 0, 0, 0, 0, 0, 0, 0);
    resln_k<<<4096, 256>>>(tgt1, tmp, nullptr, nullptr, ln1_g, ln1_b, tgt2, nullptr, nullptr);

    // ---- FFN ----
    gemm2_k<true><<<dim3(8, 32, 1), 256>>>(
        tgt2, f1_w, f1_b, ffn1, 256, 256, 256, 1024);
    // ffn2 split-K=2: z=0 -> tmp (K cols 0..511), z=1 -> tmp2 (cols 512..1023)
    gemm_k<128,64,8,4,256,false><<<dim3(4, 32, 2), 256>>>(
        ffn1, f2_w, nullptr, tmp, 512, 1024, 1024, 256,
        1,
        512,                         // sA0: advance K cols
        512, 0,                      // sB0
        (long)(tmp2 - tmp), 0,       // sC0
        0, 0);
    resln_k<<<4096, 256>>>(tgt2, tmp, tmp2, f2_b, ln3_g, ln3_b, (float*)d_out, nullptr, nullptr);
}

// round 10
// speedup vs baseline: 1.7905x; 1.5116x over previous
#include <cuda_runtime.h>
#include <math.h>

// Problem constants
#define NB    4
#define NLQ   1024
#define NC    256
#define NH    8
#define NDH   32
#define NDFF  1024
#define NLSRC 21760

// Scratch layout (floats)
#define OFF_QK    0ll
#define OFF_QKB   1048576ll     // [4096,512] q|k
#define OFF_VBW   3145728ll     // [4096,512] v in cols 0..255 (ld 512)
#define OFF_ATT   5242880ll
#define OFF_TMP   6291456ll
#define OFF_TMP2  7340032ll
#define OFF_TGT1  8388608ll
#define OFF_X     9437184ll
#define OFF_OFFAW 10485760ll    // [4096,384]
#define OFF_SAMP  12058624ll
#define OFF_TGT2  13107200ll
#define OFF_FFN1  14155776ll    // 4M
#define OFF_WCAT  18350080ll    // 384*256+384
#define OFF_VAL   18481152ll    // 22282240
#define SCRATCH_TOTAL (OFF_VAL + 22282240ll)

__device__ float g_scratch[SCRATCH_TOTAL];

// ---------------- packed fp32x2 FMA (Blackwell FFMA2) ----------------
union U64f2 { float2 f2; unsigned long long u; };
__device__ __forceinline__ float2 ffma2(float2 a, float2 b, float2 c) {
    U64f2 A, B, C, D;
    A.f2 = a; B.f2 = b; C.f2 = c;
    asm("fma.rn.f32x2 %0, %1, %2, %3;" : "=l"(D.u) : "l"(A.u), "l"(B.u), "l"(C.u));
    return D.f2;
}

// ---------------- tf32 helpers ----------------
__device__ __forceinline__ unsigned cvt_tf32(float f) {
    unsigned r; asm("cvt.rna.tf32.f32 %0, %1;" : "=r"(r) : "f"(f)); return r;
}
__device__ __forceinline__ void mma8(float* d, const unsigned* a, const unsigned* b) {
    asm("mma.sync.aligned.m16n8k8.row.col.f32.tf32.tf32.f32 "
        "{%0,%1,%2,%3},{%4,%5,%6,%7},{%8,%9},{%0,%1,%2,%3};"
        : "+f"(d[0]), "+f"(d[1]), "+f"(d[2]), "+f"(d[3])
        : "r"(a[0]), "r"(a[1]), "r"(a[2]), "r"(a[3]), "r"(b[0]), "r"(b[1]));
}

// ---------------- elementwise add ----------------
__global__ void add_k(const float* __restrict__ a, const float* __restrict__ b,
                      float* __restrict__ o, int n) {
    int i = blockIdx.x * blockDim.x + threadIdx.x;
    if (i < n) o[i] = a[i] + b[i];
}

// ---------------- weight concat (off_w | aw_w) + biases ----------------
__global__ void wcat_k(const float* __restrict__ off_w, const float* __restrict__ aw_w,
                       const float* __restrict__ off_b, const float* __restrict__ aw_b,
                       float* __restrict__ wcat) {
    int i = blockIdx.x * blockDim.x + threadIdx.x;
    if (i < 384 * 256) {
        int row = i >> 8, col = i & 255;
        wcat[i] = (row < 256) ? off_w[row * 256 + col] : aw_w[(row - 256) * 256 + col];
    } else if (i < 384 * 256 + 384) {
        int j = i - 384 * 256;
        wcat[i] = (j < 256) ? off_b[j] : aw_b[j - 256];
    }
}

// ---------------- block reduce helper (256 threads) ----------------
__device__ __forceinline__ float blockSum256(float v, float* sm) {
    #pragma unroll
    for (int o = 16; o > 0; o >>= 1) v += __shfl_xor_sync(0xffffffffu, v, o);
    __syncthreads();
    if ((threadIdx.x & 31) == 0) sm[threadIdx.x >> 5] = v;
    __syncthreads();
    return sm[0] + sm[1] + sm[2] + sm[3] + sm[4] + sm[5] + sm[6] + sm[7];
}

// ---------------- tf32 tensor-core GEMM ----------------
// C = A @ B^T + bias (weights [N,K] row-major). BM=BN=128, BK=16, 256 threads.
// 8 warps in 2(M)x4(N) grid; warp tile 64x32 via m16n8k8 tf32 mma.
// z-batched: z -> (zo=z/zdiv, zi=z%zdiv) with per-level strides.
// Requires M%128==0, N%128==0 per launch slice, K%16==0.
template<bool RELU>
__global__ void __launch_bounds__(256, 2)
gemmtc_k(const float* __restrict__ A, const float* __restrict__ Bm,
         const float* __restrict__ bias, float* __restrict__ C,
         int K, int lda, int ldb, int ldc,
         int zdiv, long sA0, long sB0, long sB1, long sC0, long sC1,
         long sb0, long sb1)
{
    __shared__ unsigned As[2][16][136];   // [k][m], PAD=136 (8 mod 32): frag loads conflict-free
    __shared__ unsigned Bs[2][16][136];   // [k][n]

    const int z = blockIdx.z;
    const long zo = z / zdiv, zi = z % zdiv;
    A  += zo * sA0;
    Bm += zo * sB0 + zi * sB1;
    C  += zo * sC0 + zi * sC1;
    if (bias) bias += zo * sb0 + zi * sb1;

    const int m0 = blockIdx.y * 128;
    const int n0 = blockIdx.x * 128;
    const int t = threadIdx.x;
    const int warp = t >> 5, lane = t & 31;
    const int wm = warp >> 2, wn = warp & 3;
    const int gid = lane >> 2, tig = lane & 3;

    float d[4][4][4];
    #pragma unroll
    for (int i = 0; i < 4; i++)
        #pragma unroll
        for (int j = 0; j < 4; j++)
            #pragma unroll
            for (int r = 0; r < 4; r++) d[i][j][r] = 0.f;

    unsigned ar[8], br[8];

    // prologue: tile 0
    #pragma unroll
    for (int i = 0; i < 8; i++) {
        int idx = t + i * 256;
        int r = idx >> 4, c = idx & 15;
        ar[i] = cvt_tf32(A[(long)(m0 + r) * lda + c]);
        br[i] = cvt_tf32(Bm[(long)(n0 + r) * ldb + c]);
    }
    #pragma unroll
    for (int i = 0; i < 8; i++) {
        int idx = t + i * 256;
        int r = idx >> 4, c = idx & 15;
        As[0][c][r] = ar[i];
        Bs[0][c][r] = br[i];
    }
    __syncthreads();

    const int nt = K >> 4;
    for (int tt = 0; tt < nt; tt++) {
        const int cur = tt & 1;
        const int k1 = (tt + 1) << 4;
        if (tt + 1 < nt) {
            #pragma unroll
            for (int i = 0; i < 8; i++) {
                int idx = t + i * 256;
                int r = idx >> 4, c = idx & 15;
                ar[i] = cvt_tf32(A[(long)(m0 + r) * lda + (k1 + c)]);
                br[i] = cvt_tf32(Bm[(long)(n0 + r) * ldb + (k1 + c)]);
            }
        }
        #pragma unroll
        for (int ks = 0; ks < 16; ks += 8) {
            unsigned af[4][4], bf[4][2];
            #pragma unroll
            for (int i = 0; i < 4; i++) {
                int mb = wm * 64 + i * 16 + gid;
                af[i][0] = As[cur][ks + tig][mb];
                af[i][1] = As[cur][ks + tig][mb + 8];
                af[i][2] = As[cur][ks + tig + 4][mb];
                af[i][3] = As[cur][ks + tig + 4][mb + 8];
            }
            #pragma unroll
            for (int j = 0; j < 4; j++) {
                int nb = wn * 32 + j * 8 + gid;
                bf[j][0] = Bs[cur][ks + tig][nb];
                bf[j][1] = Bs[cur][ks + tig + 4][nb];
            }
            #pragma unroll
            for (int i = 0; i < 4; i++)
                #pragma unroll
                for (int j = 0; j < 4; j++)
                    mma8(d[i][j], af[i], bf[j]);
        }
        if (tt + 1 < nt) {
            const int nxt = cur ^ 1;
            #pragma unroll
            for (int i = 0; i < 8; i++) {
                int idx = t + i * 256;
                int r = idx >> 4, c = idx & 15;
                As[nxt][c][r] = ar[i];
                Bs[nxt][c][r] = br[i];
            }
        }
        __syncthreads();
    }

    // epilogue
    #pragma unroll
    for (int i = 0; i < 4; i++) {
        int row = m0 + wm * 64 + i * 16 + gid;
        #pragma unroll
        for (int j = 0; j < 4; j++) {
            int col = n0 + wn * 32 + j * 8 + tig * 2;
            float b0 = bias ? bias[col] : 0.f;
            float b1 = bias ? bias[col + 1] : 0.f;
            float2 v0 = make_float2(d[i][j][0] + b0, d[i][j][1] + b1);
            float2 v1 = make_float2(d[i][j][2] + b0, d[i][j][3] + b1);
            if (RELU) {
                v0.x = fmaxf(v0.x, 0.f); v0.y = fmaxf(v0.y, 0.f);
                v1.x = fmaxf(v1.x, 0.f); v1.y = fmaxf(v1.y, 0.f);
            }
            *(float2*)&C[(long)row * ldc + col] = v0;
            *(float2*)&C[(long)(row + 8) * ldc + col] = v1;
        }
    }
}

// ---------------- flash attention (fp32, online softmax) ----------------
__global__ void __launch_bounds__(256, 2)
flash_k(const float* __restrict__ qkb, const float* __restrict__ vbw,
        float* __restrict__ out)
{
    __shared__ float Qt[32][68];
    __shared__ float Kt[32][68];
    __shared__ float Vs[64][36];
    __shared__ float Ps[64][68];

    const int z = blockIdx.z;
    const int b = z >> 3, h = z & 7;
    const int q0 = blockIdx.x * 64;
    const int t = threadIdx.x;
    const int tx = t & 15, ty = t >> 4;

    const float* Qg = qkb + ((long)(b * 1024 + q0)) * 512 + h * 32;
    const float* Kg = qkb + (long)b * 1024 * 512 + 256 + h * 32;
    const float* Vg = vbw + (long)b * 1024 * 512 + h * 32;

    const float scale = 0.1767766952966369f;

    {
        int r = t >> 2, c0 = (t & 3) * 8;
        float4 v0 = *(const float4*)(Qg + (long)r * 512 + c0);
        float4 v1 = *(const float4*)(Qg + (long)r * 512 + c0 + 4);
        Qt[c0 + 0][r] = v0.x * scale; Qt[c0 + 1][r] = v0.y * scale;
        Qt[c0 + 2][r] = v0.z * scale; Qt[c0 + 3][r] = v0.w * scale;
        Qt[c0 + 4][r] = v1.x * scale; Qt[c0 + 5][r] = v1.y * scale;
        Qt[c0 + 6][r] = v1.z * scale; Qt[c0 + 7][r] = v1.w * scale;
    }

    float m[4], l[4];
    float2 o[4];
    #pragma unroll
    for (int i = 0; i < 4; i++) { m[i] = -3.4e38f; l[i] = 0.f; o[i] = make_float2(0.f, 0.f); }

    for (int kv0 = 0; kv0 < 1024; kv0 += 64) {
        {
            int r = t >> 2, c0 = (t & 3) * 8;
            const float* kp = Kg + (long)(kv0 + r) * 512 + c0;
            float4 a = *(const float4*)kp;
            float4 bb = *(const float4*)(kp + 4);
            Kt[c0 + 0][r] = a.x;  Kt[c0 + 1][r] = a.y;
            Kt[c0 + 2][r] = a.z;  Kt[c0 + 3][r] = a.w;
            Kt[c0 + 4][r] = bb.x; Kt[c0 + 5][r] = bb.y;
            Kt[c0 + 6][r] = bb.z; Kt[c0 + 7][r] = bb.w;
            const float* vp = Vg + (long)(kv0 + r) * 512 + c0;
            *(float4*)&Vs[r][c0]     = *(const float4*)vp;
            *(float4*)&Vs[r][c0 + 4] = *(const float4*)(vp + 4);
        }
        __syncthreads();

        float2 acc[4][2];
        #pragma unroll
        for (int i = 0; i < 4; i++) { acc[i][0] = make_float2(0.f, 0.f); acc[i][1] = make_float2(0.f, 0.f); }
        #pragma unroll
        for (int kk = 0; kk < 32; kk++) {
            float4 q4 = *(const float4*)&Qt[kk][ty * 4];
            float4 k4 = *(const float4*)&Kt[kk][tx * 4];
            float2 blo = make_float2(k4.x, k4.y);
            float2 bhi = make_float2(k4.z, k4.w);
            float qa[4] = {q4.x, q4.y, q4.z, q4.w};
            #pragma unroll
            for (int i = 0; i < 4; i++) {
                float2 a2 = make_float2(qa[i], qa[i]);
                acc[i][0] = ffma2(a2, blo, acc[i][0]);
                acc[i][1] = ffma2(a2, bhi, acc[i][1]);
            }
        }

        #pragma unroll
        for (int i = 0; i < 4; i++) {
            float s0 = acc[i][0].x, s1 = acc[i][0].y, s2 = acc[i][1].x, s3 = acc[i][1].y;
            float mx = fmaxf(fmaxf(s0, s1), fmaxf(s2, s3));
            #pragma unroll
            for (int off = 1; off < 16; off <<= 1)
                mx = fmaxf(mx, __shfl_xor_sync(0xffffffffu, mx, off));
            float mnew = fmaxf(m[i], mx);
            float p0 = __expf(s0 - mnew), p1 = __expf(s1 - mnew);
            float p2 = __expf(s2 - mnew), p3 = __expf(s3 - mnew);
            float rs = p0 + p1 + p2 + p3;
            #pragma unroll
            for (int off = 1; off < 16; off <<= 1)
                rs += __shfl_xor_sync(0xffffffffu, rs, off);
            float sc_ = __expf(m[i] - mnew);
            l[i] = l[i] * sc_ + rs;
            o[i].x *= sc_; o[i].y *= sc_;
            m[i] = mnew;
            float4 pv = make_float4(p0, p1, p2, p3);
            *(float4*)&Ps[ty * 4 + i][tx * 4] = pv;
        }
        __syncthreads();

        #pragma unroll
        for (int kv = 0; kv < 64; kv += 4) {
            float2 v0 = *(const float2*)&Vs[kv + 0][tx * 2];
            float2 v1 = *(const float2*)&Vs[kv + 1][tx * 2];
            float2 v2 = *(const float2*)&Vs[kv + 2][tx * 2];
            float2 v3 = *(const float2*)&Vs[kv + 3][tx * 2];
            #pragma unroll
            for (int i = 0; i < 4; i++) {
                float4 p = *(const float4*)&Ps[ty * 4 + i][kv];
                o[i] = ffma2(make_float2(p.x, p.x), v0, o[i]);
                o[i] = ffma2(make_float2(p.y, p.y), v1, o[i]);
                o[i] = ffma2(make_float2(p.z, p.z), v2, o[i]);
                o[i] = ffma2(make_float2(p.w, p.w), v3, o[i]);
            }
        }
        __syncthreads();
    }

    #pragma unroll
    for (int i = 0; i < 4; i++) {
        float inv = 1.f / l[i];
        float2 r = make_float2(o[i].x * inv, o[i].y * inv);
        *(float2*)(out + ((long)(b * 1024 + q0 + ty * 4 + i)) * 256 + h * 32 + tx * 2) = r;
    }
}

// ---------------- residual + layernorm (general) ----------------
__global__ void resln_k(const float* __restrict__ a, const float* __restrict__ b,
                        const float* __restrict__ c, const float* __restrict__ cb,
                        const float* __restrict__ g, const float* __restrict__ be,
                        float* __restrict__ out,
                        const float* __restrict__ pos, float* __restrict__ out2)
{
    __shared__ float sm[8];
    int row = blockIdx.x, t = threadIdx.x;
    long off = (long)row * NC + t;
    float x = a[off] + b[off];
    if (c)  x += c[off];
    if (cb) x += cb[t];
    float mn = blockSum256(x, sm) * (1.f / NC);
    float d = x - mn;
    float v = blockSum256(d * d, sm) * (1.f / NC);
    float y = d * rsqrtf(v + 1e-5f) * g[t] + be[t];
    out[off] = y;
    if (out2) out2[off] = y + pos[off];
}

// ---------------- deformable sampling ----------------
__global__ void deform_k(const float* __restrict__ value,
                         const float* __restrict__ offaw,
                         const float* __restrict__ refp,
                         float* __restrict__ out)
{
    int gw   = (blockIdx.x * blockDim.x + threadIdx.x) >> 5;
    int lane = threadIdx.x & 31;
    int h  = gw & 7;
    int bq = gw >> 3;
    int b  = bq >> 10;

    const float* ap = offaw + (long)bq * 384 + 256 + h * 16;
    float w[16];
    float mx = -3.4e38f;
    #pragma unroll
    for (int j = 0; j < 16; j++) { w[j] = ap[j]; mx = fmaxf(mx, w[j]); }
    float s = 0.f;
    #pragma unroll
    for (int j = 0; j < 16; j++) { w[j] = __expf(w[j] - mx); s += w[j]; }
    float inv = 1.f / s;

    const float* op = offaw + (long)bq * 384 + h * 32;
    const float* rp = refp + (long)bq * 8;
    const float* vb = value + (long)b * NLSRC * NC + h * NDH + lane;

    const int wl_[4] = {128, 64, 32, 16};
    const int st_[4] = {0, 16384, 20480, 21504};

    float acc = 0.f;
    #pragma unroll
    for (int l = 0; l < 4; l++) {
        const int W = wl_[l], Hh = wl_[l];
        const int st = st_[l];
        float rx = rp[l * 2 + 0] * (float)W  - 0.5f;
        float ry = rp[l * 2 + 1] * (float)Hh - 0.5f;
        #pragma unroll
        for (int p = 0; p < 4; p++) {
            float a = w[l * 4 + p] * inv;
            float x = rx + op[(l * 4 + p) * 2 + 0];
            float y = ry + op[(l * 4 + p) * 2 + 1];
            float xf = floorf(x), yf = floorf(y);
            int x0 = (int)xf, y0 = (int)yf;
            float wx1 = x - xf, wy1 = y - yf;
            float wx0 = 1.f - wx1, wy0 = 1.f - wy1;
            #pragma unroll
            for (int cy = 0; cy < 2; cy++) {
                int iy = y0 + cy;
                if (iy < 0 || iy >= Hh) continue;
                float wy = cy ? wy1 : wy0;
                #pragma unroll
                for (int cx = 0; cx < 2; cx++) {
                    int ix = x0 + cx;
                    if (ix < 0 || ix >= W) continue;
                    float cw = a * wy * (cx ? wx1 : wx0);
                    acc += cw * vb[(long)(st + iy * W + ix) * NC];
                }
            }
        }
    }
    out[(long)bq * NC + h * NDH + lane] = acc;
}

extern "C" void kernel_launch(void* const* d_in, const int* in_sizes, int n_in,
                              void* d_out, int out_size)
{
    const float* tgt   = (const float*)d_in[0];
    const float* qpos  = (const float*)d_in[1];
    const float* refp  = (const float*)d_in[2];
    const float* src   = (const float*)d_in[3];
    const float* in_w  = (const float*)d_in[4];
    const float* in_b  = (const float*)d_in[5];
    const float* sa_w  = (const float*)d_in[6];
    const float* sa_b  = (const float*)d_in[7];
    const float* off_w = (const float*)d_in[8];
    const float* off_b = (const float*)d_in[9];
    const float* aw_w  = (const float*)d_in[10];
    const float* aw_b  = (const float*)d_in[11];
    const float* val_w = (const float*)d_in[12];
    const float* val_b = (const float*)d_in[13];
    const float* co_w  = (const float*)d_in[14];
    const float* co_b  = (const float*)d_in[15];
    const float* ln1_g = (const float*)d_in[16];
    const float* ln1_b = (const float*)d_in[17];
    const float* ln2_g = (const float*)d_in[18];
    const float* ln2_b = (const float*)d_in[19];
    const float* ln3_g = (const float*)d_in[20];
    const float* ln3_b = (const float*)d_in[21];
    const float* f1_w  = (const float*)d_in[22];
    const float* f1_b  = (const float*)d_in[23];
    const float* f2_w  = (const float*)d_in[24];
    const float* f2_b  = (const float*)d_in[25];

    float* S = nullptr;
    cudaGetSymbolAddress((void**)&S, g_scratch);

    float* qk    = S + OFF_QK;
    float* qkb   = S + OFF_QKB;
    float* vbw   = S + OFF_VBW;
    float* att   = S + OFF_ATT;
    float* tmp   = S + OFF_TMP;
    float* tmp2  = S + OFF_TMP2;
    float* tgt1  = S + OFF_TGT1;
    float* xq    = S + OFF_X;
    float* offaw = S + OFF_OFFAW;
    float* samp  = S + OFF_SAMP;
    float* tgt2  = S + OFF_TGT2;
    float* ffn1  = S + OFF_FFN1;
    float* wcat  = S + OFF_WCAT;
    float* valb  = S + OFF_VAL;

    // ---- self-attention ----
    add_k<<<4096, 256>>>(tgt, qpos, qk, NB * NLQ * NC);
    wcat_k<<<(384 * 256 + 384 + 255) / 256, 256>>>(off_w, aw_w, off_b, aw_b, wcat);

    // merged q|k|v projection: z=0:q, z=1:k, z=2:v  (zdiv=2 -> zo = 0,0,1; zi = 0,1,0)
    gemmtc_k<false><<<dim3(2, 32, 3), 256>>>(
        qk, in_w, in_b, qkb, 256, 256, 256, 512,
        2,
        (long)(tgt - qk),            // sA0: v uses tgt
        131072, 65536,               // sB0 (v weights), sB1 (k weights)
        (long)(vbw - qkb), 256,      // sC0 (v buffer), sC1 (k cols)
        512, 256);                   // bias strides

    // fused attention (scores + softmax + PV), fp32
    flash_k<<<dim3(16, 1, 32), 256>>>(qkb, vbw, att);

    // out projection + residual + LN2
    gemmtc_k<false><<<dim3(2, 32, 1), 256>>>(
        att, sa_w, sa_b, tmp, 256, 256, 256, 256, 1, 0, 0, 0, 0, 0, 0, 0);
    resln_k<<<4096, 256>>>(tgt, tmp, nullptr, nullptr, ln2_g, ln2_b, tgt1, qpos, xq);

    // ---- deformable cross-attention ----
    gemmtc_k<false><<<dim3(2, 680, 1), 256>>>(
        src, val_w, val_b, valb, 256, 256, 256, 256, 1, 0, 0, 0, 0, 0, 0, 0);
    // fused offsets + aw logits: N=384
    gemmtc_k<false><<<dim3(3, 32, 1), 256>>>(
        xq, wcat, wcat + 384 * 256, offaw, 256, 256, 256, 384, 1, 0, 0, 0, 0, 0, 0, 0);

    deform_k<<<4096, 256>>>(valb, offaw, refp, samp);

    gemmtc_k<false><<<dim3(2, 32, 1), 256>>>(
        samp, co_w, co_b, tmp, 256, 256, 256, 256, 1, 0, 0, 0, 0, 0, 0, 0);
    resln_k<<<4096, 256>>>(tgt1, tmp, nullptr, nullptr, ln1_g, ln1_b, tgt2, nullptr, nullptr);

    // ---- FFN ----
    gemmtc_k<true><<<dim3(8, 32, 1), 256>>>(
        tgt2, f1_w, f1_b, ffn1, 256, 256, 256, 1024, 1, 0, 0, 0, 0, 0, 0, 0);
    // ffn2 split-K=2: z=0 -> tmp (K 0..511), z=1 -> tmp2 (K 512..1023)
    gemmtc_k<false><<<dim3(2, 32, 2), 256>>>(
        ffn1, f2_w, nullptr, tmp, 512, 1024, 1024, 256,
        1,
        512,                         // sA0: advance K cols
        512, 0,                      // sB0
        (long)(tmp2 - tmp), 0,       // sC0
        0, 0);
    resln_k<<<4096, 256>>>(tgt2, tmp, tmp2, f2_b, ln3_g, ln3_b, (float*)d_out, nullptr, nullptr);
}

// round 15
// speedup vs baseline: 2.1343x; 1.1920x over previous
#include <cuda_runtime.h>
#include <math.h>

// Problem constants
#define NB    4
#define NLQ   1024
#define NC    256
#define NH    8
#define NDH   32
#define NDFF  1024
#define NLSRC 21760

// Scratch layout (floats)
#define OFF_QK    0ll
#define OFF_QKB   1048576ll     // [4096,512] q|k
#define OFF_VBW   3145728ll     // [4096,512] v in cols 0..255 (ld 512)
#define OFF_ATT   5242880ll
#define OFF_TMP   6291456ll
#define OFF_TMP2  7340032ll
#define OFF_TGT1  8388608ll
#define OFF_X     9437184ll
#define OFF_OFFAW 10485760ll    // [4096,384]
#define OFF_SAMP  12058624ll
#define OFF_TGT2  13107200ll
#define OFF_FFN1  14155776ll    // 4M
#define OFF_WCAT  18350080ll    // 384*256+384
#define OFF_VAL   18481152ll    // 22282240
#define SCRATCH_TOTAL (OFF_VAL + 22282240ll)

__device__ float g_scratch[SCRATCH_TOTAL];

// ---------------- tf32 helpers ----------------
__device__ __forceinline__ unsigned cvt_tf32(float f) {
    unsigned r; asm("cvt.rna.tf32.f32 %0, %1;" : "=r"(r) : "f"(f)); return r;
}
__device__ __forceinline__ uint4 cvt_tf32x4(float4 v) {
    return make_uint4(cvt_tf32(v.x), cvt_tf32(v.y), cvt_tf32(v.z), cvt_tf32(v.w));
}
__device__ __forceinline__ void mma8(float* d, const unsigned* a, const unsigned* b) {
    asm("mma.sync.aligned.m16n8k8.row.col.f32.tf32.tf32.f32 "
        "{%0,%1,%2,%3},{%4,%5,%6,%7},{%8,%9},{%0,%1,%2,%3};"
        : "+f"(d[0]), "+f"(d[1]), "+f"(d[2]), "+f"(d[3])
        : "r"(a[0]), "r"(a[1]), "r"(a[2]), "r"(a[3]), "r"(b[0]), "r"(b[1]));
}

// ---------------- elementwise add ----------------
__global__ void add_k(const float* __restrict__ a, const float* __restrict__ b,
                      float* __restrict__ o, int n) {
    int i = blockIdx.x * blockDim.x + threadIdx.x;
    if (i < n) o[i] = a[i] + b[i];
}

// ---------------- weight concat (off_w | aw_w) + biases ----------------
__global__ void wcat_k(const float* __restrict__ off_w, const float* __restrict__ aw_w,
                       const float* __restrict__ off_b, const float* __restrict__ aw_b,
                       float* __restrict__ wcat) {
    int i = blockIdx.x * blockDim.x + threadIdx.x;
    if (i < 384 * 256) {
        int row = i >> 8, col = i & 255;
        wcat[i] = (row < 256) ? off_w[row * 256 + col] : aw_w[(row - 256) * 256 + col];
    } else if (i < 384 * 256 + 384) {
        int j = i - 384 * 256;
        wcat[i] = (j < 256) ? off_b[j] : aw_b[j - 256];
    }
}

// ---------------- block reduce helper (256 threads) ----------------
__device__ __forceinline__ float blockSum256(float v, float* sm) {
    #pragma unroll
    for (int o = 16; o > 0; o >>= 1) v += __shfl_xor_sync(0xffffffffu, v, o);
    __syncthreads();
    if ((threadIdx.x & 31) == 0) sm[threadIdx.x >> 5] = v;
    __syncthreads();
    return sm[0] + sm[1] + sm[2] + sm[3] + sm[4] + sm[5] + sm[6] + sm[7];
}

// ---------------- tf32 tensor-core GEMM ----------------
// C = A @ B^T + bias (weights [N,K] row-major). BM=BN=128, BK=16, 256 threads.
template<bool RELU>
__global__ void __launch_bounds__(256, 2)
gemmtc_k(const float* __restrict__ A, const float* __restrict__ Bm,
         const float* __restrict__ bias, float* __restrict__ C,
         int K, int lda, int ldb, int ldc,
         int zdiv, long sA0, long sB0, long sB1, long sC0, long sC1,
         long sb0, long sb1)
{
    __shared__ unsigned As[2][16][136];
    __shared__ unsigned Bs[2][16][136];

    const int z = blockIdx.z;
    const long zo = z / zdiv, zi = z % zdiv;
    A  += zo * sA0;
    Bm += zo * sB0 + zi * sB1;
    C  += zo * sC0 + zi * sC1;
    if (bias) bias += zo * sb0 + zi * sb1;

    const int m0 = blockIdx.y * 128;
    const int n0 = blockIdx.x * 128;
    const int t = threadIdx.x;
    const int warp = t >> 5, lane = t & 31;
    const int wm = warp >> 2, wn = warp & 3;
    const int gid = lane >> 2, tig = lane & 3;

    float d[4][4][4];
    #pragma unroll
    for (int i = 0; i < 4; i++)
        #pragma unroll
        for (int j = 0; j < 4; j++)
            #pragma unroll
            for (int r = 0; r < 4; r++) d[i][j][r] = 0.f;

    unsigned ar[8], br[8];

    #pragma unroll
    for (int i = 0; i < 8; i++) {
        int idx = t + i * 256;
        int r = idx >> 4, c = idx & 15;
        ar[i] = cvt_tf32(A[(long)(m0 + r) * lda + c]);
        br[i] = cvt_tf32(Bm[(long)(n0 + r) * ldb + c]);
    }
    #pragma unroll
    for (int i = 0; i < 8; i++) {
        int idx = t + i * 256;
        int r = idx >> 4, c = idx & 15;
        As[0][c][r] = ar[i];
        Bs[0][c][r] = br[i];
    }
    __syncthreads();

    const int nt = K >> 4;
    for (int tt = 0; tt < nt; tt++) {
        const int cur = tt & 1;
        const int k1 = (tt + 1) << 4;
        if (tt + 1 < nt) {
            #pragma unroll
            for (int i = 0; i < 8; i++) {
                int idx = t + i * 256;
                int r = idx >> 4, c = idx & 15;
                ar[i] = cvt_tf32(A[(long)(m0 + r) * lda + (k1 + c)]);
                br[i] = cvt_tf32(Bm[(long)(n0 + r) * ldb + (k1 + c)]);
            }
        }
        #pragma unroll
        for (int ks = 0; ks < 16; ks += 8) {
            unsigned af[4][4], bf[4][2];
            #pragma unroll
            for (int i = 0; i < 4; i++) {
                int mb = wm * 64 + i * 16 + gid;
                af[i][0] = As[cur][ks + tig][mb];
                af[i][1] = As[cur][ks + tig][mb + 8];
                af[i][2] = As[cur][ks + tig + 4][mb];
                af[i][3] = As[cur][ks + tig + 4][mb + 8];
            }
            #pragma unroll
            for (int j = 0; j < 4; j++) {
                int nb = wn * 32 + j * 8 + gid;
                bf[j][0] = Bs[cur][ks + tig][nb];
                bf[j][1] = Bs[cur][ks + tig + 4][nb];
            }
            #pragma unroll
            for (int i = 0; i < 4; i++)
                #pragma unroll
                for (int j = 0; j < 4; j++)
                    mma8(d[i][j], af[i], bf[j]);
        }
        if (tt + 1 < nt) {
            const int nxt = cur ^ 1;
            #pragma unroll
            for (int i = 0; i < 8; i++) {
                int idx = t + i * 256;
                int r = idx >> 4, c = idx & 15;
                As[nxt][c][r] = ar[i];
                Bs[nxt][c][r] = br[i];
            }
        }
        __syncthreads();
    }

    #pragma unroll
    for (int i = 0; i < 4; i++) {
        int row = m0 + wm * 64 + i * 16 + gid;
        #pragma unroll
        for (int j = 0; j < 4; j++) {
            int col = n0 + wn * 32 + j * 8 + tig * 2;
            float b0 = bias ? bias[col] : 0.f;
            float b1 = bias ? bias[col + 1] : 0.f;
            float2 v0 = make_float2(d[i][j][0] + b0, d[i][j][1] + b1);
            float2 v1 = make_float2(d[i][j][2] + b0, d[i][j][3] + b1);
            if (RELU) {
                v0.x = fmaxf(v0.x, 0.f); v0.y = fmaxf(v0.y, 0.f);
                v1.x = fmaxf(v1.x, 0.f); v1.y = fmaxf(v1.y, 0.f);
            }
            *(float2*)&C[(long)row * ldc + col] = v0;
            *(float2*)&C[(long)(row + 8) * ldc + col] = v1;
        }
    }
}

// ---------------- tf32 flash attention ----------------
// 128 threads = 4 warps; each warp owns 16 q rows; block = 64 q rows; kv chunks of 64.
// S accumulators live in m16n8k8 C-fragments; softmax via quad shuffles;
// P round-trips smem (tf32) to become the PV A-fragment.
__global__ void __launch_bounds__(128, 4)
flashtc_k(const float* __restrict__ qkb, const float* __restrict__ vbw,
          float* __restrict__ out)
{
    __shared__ unsigned Qs[64][36];   // [q][dh]   tf32
    __shared__ unsigned Ks[64][36];   // [kv][dh]  tf32
    __shared__ unsigned Vs[64][40];   // [kv][dh]  tf32
    __shared__ unsigned Ps[64][68];   // [q][kv]   tf32

    const int z = blockIdx.z;
    const int b = z >> 3, h = z & 7;
    const int q0 = blockIdx.x * 64;
    const int t = threadIdx.x;
    const int warp = t >> 5, lane = t & 31;
    const int gid = lane >> 2, tig = lane & 3;
    const int wq = warp * 16;

    const float* Qg = qkb + (long)(b * 1024 + q0) * 512 + h * 32;
    const float* Kg = qkb + (long)b * 1024 * 512 + 256 + h * 32;
    const float* Vg = vbw + (long)b * 1024 * 512 + h * 32;
    const float scale = 0.1767766952966369f;

    // load Q tile (scaled, tf32): thread -> row t>>1, 16 cols
    {
        int r = t >> 1, c = (t & 1) * 16;
        #pragma unroll
        for (int j = 0; j < 16; j += 4) {
            float4 v = *(const float4*)(Qg + (long)r * 512 + c + j);
            v.x *= scale; v.y *= scale; v.z *= scale; v.w *= scale;
            *(uint4*)&Qs[r][c + j] = cvt_tf32x4(v);
        }
    }

    float m0 = -3.4e38f, m1 = -3.4e38f, l0 = 0.f, l1 = 0.f;
    float o[4][4];
    #pragma unroll
    for (int nt = 0; nt < 4; nt++)
        #pragma unroll
        for (int r = 0; r < 4; r++) o[nt][r] = 0.f;

    for (int kv0 = 0; kv0 < 1024; kv0 += 64) {
        __syncthreads();   // previous chunk's readers done
        {
            int r = t >> 1, c = (t & 1) * 16;
            #pragma unroll
            for (int j = 0; j < 16; j += 4) {
                float4 kv4 = *(const float4*)(Kg + (long)(kv0 + r) * 512 + c + j);
                *(uint4*)&Ks[r][c + j] = cvt_tf32x4(kv4);
                float4 vv4 = *(const float4*)(Vg + (long)(kv0 + r) * 512 + c + j);
                *(uint4*)&Vs[r][c + j] = cvt_tf32x4(vv4);
            }
        }
        __syncthreads();

        // ---- S = Q K^T : warp tile m16 x n64, k32 ----
        float sc[8][4];
        #pragma unroll
        for (int nt = 0; nt < 8; nt++)
            #pragma unroll
            for (int r = 0; r < 4; r++) sc[nt][r] = 0.f;
        #pragma unroll
        for (int ks = 0; ks < 4; ks++) {
            unsigned af[4];
            af[0] = Qs[wq + gid][ks * 8 + tig];
            af[1] = Qs[wq + gid + 8][ks * 8 + tig];
            af[2] = Qs[wq + gid][ks * 8 + tig + 4];
            af[3] = Qs[wq + gid + 8][ks * 8 + tig + 4];
            #pragma unroll
            for (int nt = 0; nt < 8; nt++) {
                unsigned bf[2];
                bf[0] = Ks[nt * 8 + gid][ks * 8 + tig];
                bf[1] = Ks[nt * 8 + gid][ks * 8 + tig + 4];
                mma8(sc[nt], af, bf);
            }
        }

        // ---- online softmax on fragments (rows gid, gid+8) ----
        float mx0 = -3.4e38f, mx1 = -3.4e38f;
        #pragma unroll
        for (int nt = 0; nt < 8; nt++) {
            mx0 = fmaxf(mx0, fmaxf(sc[nt][0], sc[nt][1]));
            mx1 = fmaxf(mx1, fmaxf(sc[nt][2], sc[nt][3]));
        }
        mx0 = fmaxf(mx0, __shfl_xor_sync(0xffffffffu, mx0, 1));
        mx0 = fmaxf(mx0, __shfl_xor_sync(0xffffffffu, mx0, 2));
        mx1 = fmaxf(mx1, __shfl_xor_sync(0xffffffffu, mx1, 1));
        mx1 = fmaxf(mx1, __shfl_xor_sync(0xffffffffu, mx1, 2));
        float mn0 = fmaxf(m0, mx0), mn1 = fmaxf(m1, mx1);
        float rs0 = 0.f, rs1 = 0.f;
        #pragma unroll
        for (int nt = 0; nt < 8; nt++) {
            float p0 = __expf(sc[nt][0] - mn0);
            float p1 = __expf(sc[nt][1] - mn0);
            float p2 = __expf(sc[nt][2] - mn1);
            float p3 = __expf(sc[nt][3] - mn1);
            rs0 += p0 + p1; rs1 += p2 + p3;
            *(uint2*)&Ps[wq + gid][nt * 8 + 2 * tig]     = make_uint2(cvt_tf32(p0), cvt_tf32(p1));
            *(uint2*)&Ps[wq + gid + 8][nt * 8 + 2 * tig] = make_uint2(cvt_tf32(p2), cvt_tf32(p3));
        }
        rs0 += __shfl_xor_sync(0xffffffffu, rs0, 1);
        rs0 += __shfl_xor_sync(0xffffffffu, rs0, 2);
        rs1 += __shfl_xor_sync(0xffffffffu, rs1, 1);
        rs1 += __shfl_xor_sync(0xffffffffu, rs1, 2);
        float e0 = __expf(m0 - mn0), e1 = __expf(m1 - mn1);
        l0 = l0 * e0 + rs0; l1 = l1 * e1 + rs1;
        m0 = mn0; m1 = mn1;
        #pragma unroll
        for (int nt = 0; nt < 4; nt++) {
            o[nt][0] *= e0; o[nt][1] *= e0;
            o[nt][2] *= e1; o[nt][3] *= e1;
        }
        __syncwarp();   // Ps visible across lanes of this warp

        // ---- O += P V : m16 x n32 x k64 ----
        #pragma unroll
        for (int ks = 0; ks < 8; ks++) {
            unsigned af[4];
            af[0] = Ps[wq + gid][ks * 8 + tig];
            af[1] = Ps[wq + gid + 8][ks * 8 + tig];
            af[2] = Ps[wq + gid][ks * 8 + tig + 4];
            af[3] = Ps[wq + gid + 8][ks * 8 + tig + 4];
            #pragma unroll
            for (int nt = 0; nt < 4; nt++) {
                unsigned bf[2];
                bf[0] = Vs[ks * 8 + tig][nt * 8 + gid];
                bf[1] = Vs[ks * 8 + tig + 4][nt * 8 + gid];
                mma8(o[nt], af, bf);
            }
        }
    }

    // epilogue
    float i0 = 1.f / l0, i1 = 1.f / l1;
    long row0 = (long)(b * 1024 + q0 + wq + gid);
    #pragma unroll
    for (int nt = 0; nt < 4; nt++) {
        int col = h * 32 + nt * 8 + 2 * tig;
        *(float2*)&out[row0 * 256 + col]       = make_float2(o[nt][0] * i0, o[nt][1] * i0);
        *(float2*)&out[(row0 + 8) * 256 + col] = make_float2(o[nt][2] * i1, o[nt][3] * i1);
    }
}

// ---------------- residual + layernorm (general) ----------------
__global__ void resln_k(const float* __restrict__ a, const float* __restrict__ b,
                        const float* __restrict__ c, const float* __restrict__ cb,
                        const float* __restrict__ g, const float* __restrict__ be,
                        float* __restrict__ out,
                        const float* __restrict__ pos, float* __restrict__ out2)
{
    __shared__ float sm[8];
    int row = blockIdx.x, t = threadIdx.x;
    long off = (long)row * NC + t;
    float x = a[off] + b[off];
    if (c)  x += c[off];
    if (cb) x += cb[t];
    float mn = blockSum256(x, sm) * (1.f / NC);
    float d = x - mn;
    float v = blockSum256(d * d, sm) * (1.f / NC);
    float y = d * rsqrtf(v + 1e-5f) * g[t] + be[t];
    out[off] = y;
    if (out2) out2[off] = y + pos[off];
}

// ---------------- deformable sampling ----------------
__global__ void deform_k(const float* __restrict__ value,
                         const float* __restrict__ offaw,
                         const float* __restrict__ refp,
                         float* __restrict__ out)
{
    int gw   = (blockIdx.x * blockDim.x + threadIdx.x) >> 5;
    int lane = threadIdx.x & 31;
    int h  = gw & 7;
    int bq = gw >> 3;
    int b  = bq >> 10;

    const float* ap = offaw + (long)bq * 384 + 256 + h * 16;
    float w[16];
    float mx = -3.4e38f;
    #pragma unroll
    for (int j = 0; j < 16; j++) { w[j] = ap[j]; mx = fmaxf(mx, w[j]); }
    float s = 0.f;
    #pragma unroll
    for (int j = 0; j < 16; j++) { w[j] = __expf(w[j] - mx); s += w[j]; }
    float inv = 1.f / s;

    const float* op = offaw + (long)bq * 384 + h * 32;
    const float* rp = refp + (long)bq * 8;
    const float* vb = value + (long)b * NLSRC * NC + h * NDH + lane;

    const int wl_[4] = {128, 64, 32, 16};
    const int st_[4] = {0, 16384, 20480, 21504};

    float acc = 0.f;
    #pragma unroll
    for (int l = 0; l < 4; l++) {
        const int W = wl_[l], Hh = wl_[l];
        const int st = st_[l];
        float rx = rp[l * 2 + 0] * (float)W  - 0.5f;
        float ry = rp[l * 2 + 1] * (float)Hh - 0.5f;
        #pragma unroll
        for (int p = 0; p < 4; p++) {
            float a = w[l * 4 + p] * inv;
            float x = rx + op[(l * 4 + p) * 2 + 0];
            float y = ry + op[(l * 4 + p) * 2 + 1];
            float xf = floorf(x), yf = floorf(y);
            int x0 = (int)xf, y0 = (int)yf;
            float wx1 = x - xf, wy1 = y - yf;
            float wx0 = 1.f - wx1, wy0 = 1.f - wy1;
            #pragma unroll
            for (int cy = 0; cy < 2; cy++) {
                int iy = y0 + cy;
                if (iy < 0 || iy >= Hh) continue;
                float wy = cy ? wy1 : wy0;
                #pragma unroll
                for (int cx = 0; cx < 2; cx++) {
                    int ix = x0 + cx;
                    if (ix < 0 || ix >= W) continue;
                    float cw = a * wy * (cx ? wx1 : wx0);
                    acc += cw * vb[(long)(st + iy * W + ix) * NC];
                }
            }
        }
    }
    out[(long)bq * NC + h * NDH + lane] = acc;
}

extern "C" void kernel_launch(void* const* d_in, const int* in_sizes, int n_in,
                              void* d_out, int out_size)
{
    const float* tgt   = (const float*)d_in[0];
    const float* qpos  = (const float*)d_in[1];
    const float* refp  = (const float*)d_in[2];
    const float* src   = (const float*)d_in[3];
    const float* in_w  = (const float*)d_in[4];
    const float* in_b  = (const float*)d_in[5];
    const float* sa_w  = (const float*)d_in[6];
    const float* sa_b  = (const float*)d_in[7];
    const float* off_w = (const float*)d_in[8];
    const float* off_b = (const float*)d_in[9];
    const float* aw_w  = (const float*)d_in[10];
    const float* aw_b  = (const float*)d_in[11];
    const float* val_w = (const float*)d_in[12];
    const float* val_b = (const float*)d_in[13];
    const float* co_w  = (const float*)d_in[14];
    const float* co_b  = (const float*)d_in[15];
    const float* ln1_g = (const float*)d_in[16];
    const float* ln1_b = (const float*)d_in[17];
    const float* ln2_g = (const float*)d_in[18];
    const float* ln2_b = (const float*)d_in[19];
    const float* ln3_g = (const float*)d_in[20];
    const float* ln3_b = (const float*)d_in[21];
    const float* f1_w  = (const float*)d_in[22];
    const float* f1_b  = (const float*)d_in[23];
    const float* f2_w  = (const float*)d_in[24];
    const float* f2_b  = (const float*)d_in[25];

    float* S = nullptr;
    cudaGetSymbolAddress((void**)&S, g_scratch);

    float* qk    = S + OFF_QK;
    float* qkb   = S + OFF_QKB;
    float* vbw   = S + OFF_VBW;
    float* att   = S + OFF_ATT;
    float* tmp   = S + OFF_TMP;
    float* tmp2  = S + OFF_TMP2;
    float* tgt1  = S + OFF_TGT1;
    float* xq    = S + OFF_X;
    float* offaw = S + OFF_OFFAW;
    float* samp  = S + OFF_SAMP;
    float* tgt2  = S + OFF_TGT2;
    float* ffn1  = S + OFF_FFN1;
    float* wcat  = S + OFF_WCAT;
    float* valb  = S + OFF_VAL;

    // ---- self-attention ----
    add_k<<<4096, 256>>>(tgt, qpos, qk, NB * NLQ * NC);
    wcat_k<<<(384 * 256 + 384 + 255) / 256, 256>>>(off_w, aw_w, off_b, aw_b, wcat);

    // merged q|k|v projection: z=0:q, z=1:k, z=2:v  (zdiv=2 -> zo = 0,0,1; zi = 0,1,0)
    gemmtc_k<false><<<dim3(2, 32, 3), 256>>>(
        qk, in_w, in_b, qkb, 256, 256, 256, 512,
        2,
        (long)(tgt - qk),            // sA0: v uses tgt
        131072, 65536,               // sB0 (v weights), sB1 (k weights)
        (long)(vbw - qkb), 256,      // sC0 (v buffer), sC1 (k cols)
        512, 256);                   // bias strides

    // fused attention (scores + softmax + PV), tf32 tensor cores
    flashtc_k<<<dim3(16, 1, 32), 128>>>(qkb, vbw, att);

    // out projection + residual + LN2
    gemmtc_k<false><<<dim3(2, 32, 1), 256>>>(
        att, sa_w, sa_b, tmp, 256, 256, 256, 256, 1, 0, 0, 0, 0, 0, 0, 0);
    resln_k<<<4096, 256>>>(tgt, tmp, nullptr, nullptr, ln2_g, ln2_b, tgt1, qpos, xq);

    // ---- deformable cross-attention ----
    gemmtc_k<false><<<dim3(2, 680, 1), 256>>>(
        src, val_w, val_b, valb, 256, 256, 256, 256, 1, 0, 0, 0, 0, 0, 0, 0);
    // fused offsets + aw logits: N=384
    gemmtc_k<false><<<dim3(3, 32, 1), 256>>>(
        xq, wcat, wcat + 384 * 256, offaw, 256, 256, 256, 384, 1, 0, 0, 0, 0, 0, 0, 0);

    deform_k<<<4096, 256>>>(valb, offaw, refp, samp);

    gemmtc_k<false><<<dim3(2, 32, 1), 256>>>(
        samp, co_w, co_b, tmp, 256, 256, 256, 256, 1, 0, 0, 0, 0, 0, 0, 0);
    resln_k<<<4096, 256>>>(tgt1, tmp, nullptr, nullptr, ln1_g, ln1_b, tgt2, nullptr, nullptr);

    // ---- FFN ----
    gemmtc_k<true><<<dim3(8, 32, 1), 256>>>(
        tgt2, f1_w, f1_b, ffn1, 256, 256, 256, 1024, 1, 0, 0, 0, 0, 0, 0, 0);
    // ffn2 split-K=2: z=0 -> tmp (K 0..511), z=1 -> tmp2 (K 512..1023)
    gemmtc_k<false><<<dim3(2, 32, 2), 256>>>(
        ffn1, f2_w, nullptr, tmp, 512, 1024, 1024, 256,
        1,
        512,                         // sA0: advance K cols
        512, 0,                      // sB0
        (long)(tmp2 - tmp), 0,       // sC0
        0, 0);
    resln_k<<<4096, 256>>>(tgt2, tmp, tmp2, f2_b, ln3_g, ln3_b, (float*)d_out, nullptr, nullptr);
}

// round 16
// speedup vs baseline: 2.1881x; 1.0252x over previous
#include <cuda_runtime.h>
#include <math.h>

// Problem constants
#define NB    4
#define NLQ   1024
#define NC    256
#define NH    8
#define NDH   32
#define NDFF  1024
#define NLSRC 21760

// Scratch layout (floats)
#define OFF_QK    0ll
#define OFF_QKB   1048576ll     // [4096,512] q|k
#define OFF_VBW   3145728ll     // [4096,512] v in cols 0..255 (ld 512)
#define OFF_ATT   5242880ll
#define OFF_TMP   6291456ll
#define OFF_TMP2  7340032ll
#define OFF_TGT1  8388608ll
#define OFF_X     9437184ll
#define OFF_OFFAW 10485760ll    // [4096,384]
#define OFF_SAMP  12058624ll
#define OFF_TGT2  13107200ll
#define OFF_FFN1  14155776ll    // 4M
#define OFF_WCAT  18350080ll    // 384*256+384
#define OFF_VAL   18481152ll    // 22282240
#define SCRATCH_TOTAL (OFF_VAL + 22282240ll)

__device__ float g_scratch[SCRATCH_TOTAL];

// ---------------- tf32 helpers ----------------
__device__ __forceinline__ unsigned cvt_tf32(float f) {
    unsigned r; asm("cvt.rna.tf32.f32 %0, %1;" : "=r"(r) : "f"(f)); return r;
}
__device__ __forceinline__ uint4 cvt_tf32x4(float4 v) {
    return make_uint4(cvt_tf32(v.x), cvt_tf32(v.y), cvt_tf32(v.z), cvt_tf32(v.w));
}
__device__ __forceinline__ void mma8(float* d, const unsigned* a, const unsigned* b) {
    asm("mma.sync.aligned.m16n8k8.row.col.f32.tf32.tf32.f32 "
        "{%0,%1,%2,%3},{%4,%5,%6,%7},{%8,%9},{%0,%1,%2,%3};"
        : "+f"(d[0]), "+f"(d[1]), "+f"(d[2]), "+f"(d[3])
        : "r"(a[0]), "r"(a[1]), "r"(a[2]), "r"(a[3]), "r"(b[0]), "r"(b[1]));
}
// bank swizzle for [k][m] tiles: makes STS conflict-free, keeps frag LDS conflict-free
__device__ __forceinline__ int swz(int k) { return ((k >> 2) & 3) << 1; }

// ---------------- elementwise add ----------------
__global__ void add_k(const float* __restrict__ a, const float* __restrict__ b,
                      float* __restrict__ o, int n) {
    int i = blockIdx.x * blockDim.x + threadIdx.x;
    if (i < n) o[i] = a[i] + b[i];
}

// ---------------- weight concat (off_w | aw_w) + biases ----------------
__global__ void wcat_k(const float* __restrict__ off_w, const float* __restrict__ aw_w,
                       const float* __restrict__ off_b, const float* __restrict__ aw_b,
                       float* __restrict__ wcat) {
    int i = blockIdx.x * blockDim.x + threadIdx.x;
    if (i < 384 * 256) {
        int row = i >> 8, col = i & 255;
        wcat[i] = (row < 256) ? off_w[row * 256 + col] : aw_w[(row - 256) * 256 + col];
    } else if (i < 384 * 256 + 384) {
        int j = i - 384 * 256;
        wcat[i] = (j < 256) ? off_b[j] : aw_b[j - 256];
    }
}

// ---------------- block reduce helper (256 threads) ----------------
__device__ __forceinline__ float blockSum256(float v, float* sm) {
    #pragma unroll
    for (int o = 16; o > 0; o >>= 1) v += __shfl_xor_sync(0xffffffffu, v, o);
    __syncthreads();
    if ((threadIdx.x & 31) == 0) sm[threadIdx.x >> 5] = v;
    __syncthreads();
    return sm[0] + sm[1] + sm[2] + sm[3] + sm[4] + sm[5] + sm[6] + sm[7];
}

// ---------------- tf32 tensor-core GEMM (bank-conflict-free stores) ----------------
// C = A @ B^T + bias (weights [N,K] row-major). BM=BN=128, BK=16, 256 threads.
template<bool RELU>
__global__ void __launch_bounds__(256, 2)
gemmtc_k(const float* __restrict__ A, const float* __restrict__ Bm,
         const float* __restrict__ bias, float* __restrict__ C,
         int K, int lda, int ldb, int ldc,
         int zdiv, long sA0, long sB0, long sB1, long sC0, long sC1,
         long sb0, long sb1)
{
    __shared__ unsigned As[2][16][136];
    __shared__ unsigned Bs[2][16][136];

    const int z = blockIdx.z;
    const long zo = z / zdiv, zi = z % zdiv;
    A  += zo * sA0;
    Bm += zo * sB0 + zi * sB1;
    C  += zo * sC0 + zi * sC1;
    if (bias) bias += zo * sb0 + zi * sb1;

    const int m0 = blockIdx.y * 128;
    const int n0 = blockIdx.x * 128;
    const int t = threadIdx.x;
    const int warp = t >> 5, lane = t & 31;
    const int wm = warp >> 2, wn = warp & 3;
    const int gid = lane >> 2, tig = lane & 3;

    float d[4][4][4];
    #pragma unroll
    for (int i = 0; i < 4; i++)
        #pragma unroll
        for (int j = 0; j < 4; j++)
            #pragma unroll
            for (int r = 0; r < 4; r++) d[i][j][r] = 0.f;

    unsigned ar[8], br[8];

    #pragma unroll
    for (int i = 0; i < 8; i++) {
        int idx = t + i * 256;
        int r = idx >> 4, c = idx & 15;
        ar[i] = cvt_tf32(A[(long)(m0 + r) * lda + c]);
        br[i] = cvt_tf32(Bm[(long)(n0 + r) * ldb + c]);
    }
    #pragma unroll
    for (int i = 0; i < 8; i++) {
        int idx = t + i * 256;
        int r = idx >> 4, c = idx & 15;
        As[0][c][r ^ swz(c)] = ar[i];
        Bs[0][c][r ^ swz(c)] = br[i];
    }
    __syncthreads();

    const int nt = K >> 4;
    for (int tt = 0; tt < nt; tt++) {
        const int cur = tt & 1;
        const int k1 = (tt + 1) << 4;
        if (tt + 1 < nt) {
            #pragma unroll
            for (int i = 0; i < 8; i++) {
                int idx = t + i * 256;
                int r = idx >> 4, c = idx & 15;
                ar[i] = cvt_tf32(A[(long)(m0 + r) * lda + (k1 + c)]);
                br[i] = cvt_tf32(Bm[(long)(n0 + r) * ldb + (k1 + c)]);
            }
        }
        #pragma unroll
        for (int ks = 0; ks < 16; ks += 8) {
            const int ka = ks + tig, kb = ks + tig + 4;
            const int s0 = swz(ka), s1 = swz(kb);
            unsigned af[4][4], bf[4][2];
            #pragma unroll
            for (int i = 0; i < 4; i++) {
                int mb = wm * 64 + i * 16 + gid;
                af[i][0] = As[cur][ka][mb ^ s0];
                af[i][1] = As[cur][ka][(mb + 8) ^ s0];
                af[i][2] = As[cur][kb][mb ^ s1];
                af[i][3] = As[cur][kb][(mb + 8) ^ s1];
            }
            #pragma unroll
            for (int j = 0; j < 4; j++) {
                int nb = wn * 32 + j * 8 + gid;
                bf[j][0] = Bs[cur][ka][nb ^ s0];
                bf[j][1] = Bs[cur][kb][nb ^ s1];
            }
            #pragma unroll
            for (int i = 0; i < 4; i++)
                #pragma unroll
                for (int j = 0; j < 4; j++)
                    mma8(d[i][j], af[i], bf[j]);
        }
        if (tt + 1 < nt) {
            const int nxt = cur ^ 1;
            #pragma unroll
            for (int i = 0; i < 8; i++) {
                int idx = t + i * 256;
                int r = idx >> 4, c = idx & 15;
                As[nxt][c][r ^ swz(c)] = ar[i];
                Bs[nxt][c][r ^ swz(c)] = br[i];
            }
        }
        __syncthreads();
    }

    #pragma unroll
    for (int i = 0; i < 4; i++) {
        int row = m0 + wm * 64 + i * 16 + gid;
        #pragma unroll
        for (int j = 0; j < 4; j++) {
            int col = n0 + wn * 32 + j * 8 + tig * 2;
            float b0 = bias ? bias[col] : 0.f;
            float b1 = bias ? bias[col + 1] : 0.f;
            float2 v0 = make_float2(d[i][j][0] + b0, d[i][j][1] + b1);
            float2 v1 = make_float2(d[i][j][2] + b0, d[i][j][3] + b1);
            if (RELU) {
                v0.x = fmaxf(v0.x, 0.f); v0.y = fmaxf(v0.y, 0.f);
                v1.x = fmaxf(v1.x, 0.f); v1.y = fmaxf(v1.y, 0.f);
            }
            *(float2*)&C[(long)row * ldc + col] = v0;
            *(float2*)&C[(long)(row + 8) * ldc + col] = v1;
        }
    }
}

// ---------------- tf32 flash attention ----------------
__global__ void __launch_bounds__(128, 4)
flashtc_k(const float* __restrict__ qkb, const float* __restrict__ vbw,
          float* __restrict__ out)
{
    __shared__ unsigned Qs[64][36];   // [q][dh]   tf32
    __shared__ unsigned Ks[64][36];   // [kv][dh]  tf32
    __shared__ unsigned Vs[64][40];   // [kv][dh]  tf32
    __shared__ unsigned Ps[64][68];   // [q][kv]   tf32

    const int z = blockIdx.z;
    const int b = z >> 3, h = z & 7;
    const int q0 = blockIdx.x * 64;
    const int t = threadIdx.x;
    const int warp = t >> 5, lane = t & 31;
    const int gid = lane >> 2, tig = lane & 3;
    const int wq = warp * 16;

    const float* Qg = qkb + (long)(b * 1024 + q0) * 512 + h * 32;
    const float* Kg = qkb + (long)b * 1024 * 512 + 256 + h * 32;
    const float* Vg = vbw + (long)b * 1024 * 512 + h * 32;
    const float scale = 0.1767766952966369f;

    {
        int r = t >> 1, c = (t & 1) * 16;
        #pragma unroll
        for (int j = 0; j < 16; j += 4) {
            float4 v = *(const float4*)(Qg + (long)r * 512 + c + j);
            v.x *= scale; v.y *= scale; v.z *= scale; v.w *= scale;
            *(uint4*)&Qs[r][c + j] = cvt_tf32x4(v);
        }
    }

    float m0 = -3.4e38f, m1 = -3.4e38f, l0 = 0.f, l1 = 0.f;
    float o[4][4];
    #pragma unroll
    for (int nt = 0; nt < 4; nt++)
        #pragma unroll
        for (int r = 0; r < 4; r++) o[nt][r] = 0.f;

    for (int kv0 = 0; kv0 < 1024; kv0 += 64) {
        __syncthreads();
        {
            int r = t >> 1, c = (t & 1) * 16;
            #pragma unroll
            for (int j = 0; j < 16; j += 4) {
                float4 kv4 = *(const float4*)(Kg + (long)(kv0 + r) * 512 + c + j);
                *(uint4*)&Ks[r][c + j] = cvt_tf32x4(kv4);
                float4 vv4 = *(const float4*)(Vg + (long)(kv0 + r) * 512 + c + j);
                *(uint4*)&Vs[r][c + j] = cvt_tf32x4(vv4);
            }
        }
        __syncthreads();

        float sc[8][4];
        #pragma unroll
        for (int nt = 0; nt < 8; nt++)
            #pragma unroll
            for (int r = 0; r < 4; r++) sc[nt][r] = 0.f;
        #pragma unroll
        for (int ks = 0; ks < 4; ks++) {
            unsigned af[4];
            af[0] = Qs[wq + gid][ks * 8 + tig];
            af[1] = Qs[wq + gid + 8][ks * 8 + tig];
            af[2] = Qs[wq + gid][ks * 8 + tig + 4];
            af[3] = Qs[wq + gid + 8][ks * 8 + tig + 4];
            #pragma unroll
            for (int nt = 0; nt < 8; nt++) {
                unsigned bf[2];
                bf[0] = Ks[nt * 8 + gid][ks * 8 + tig];
                bf[1] = Ks[nt * 8 + gid][ks * 8 + tig + 4];
                mma8(sc[nt], af, bf);
            }
        }

        float mx0 = -3.4e38f, mx1 = -3.4e38f;
        #pragma unroll
        for (int nt = 0; nt < 8; nt++) {
            mx0 = fmaxf(mx0, fmaxf(sc[nt][0], sc[nt][1]));
            mx1 = fmaxf(mx1, fmaxf(sc[nt][2], sc[nt][3]));
        }
        mx0 = fmaxf(mx0, __shfl_xor_sync(0xffffffffu, mx0, 1));
        mx0 = fmaxf(mx0, __shfl_xor_sync(0xffffffffu, mx0, 2));
        mx1 = fmaxf(mx1, __shfl_xor_sync(0xffffffffu, mx1, 1));
        mx1 = fmaxf(mx1, __shfl_xor_sync(0xffffffffu, mx1, 2));
        float mn0 = fmaxf(m0, mx0), mn1 = fmaxf(m1, mx1);
        float rs0 = 0.f, rs1 = 0.f;
        #pragma unroll
        for (int nt = 0; nt < 8; nt++) {
            float p0 = __expf(sc[nt][0] - mn0);
            float p1 = __expf(sc[nt][1] - mn0);
            float p2 = __expf(sc[nt][2] - mn1);
            float p3 = __expf(sc[nt][3] - mn1);
            rs0 += p0 + p1; rs1 += p2 + p3;
            *(uint2*)&Ps[wq + gid][nt * 8 + 2 * tig]     = make_uint2(cvt_tf32(p0), cvt_tf32(p1));
            *(uint2*)&Ps[wq + gid + 8][nt * 8 + 2 * tig] = make_uint2(cvt_tf32(p2), cvt_tf32(p3));
        }
        rs0 += __shfl_xor_sync(0xffffffffu, rs0, 1);
        rs0 += __shfl_xor_sync(0xffffffffu, rs0, 2);
        rs1 += __shfl_xor_sync(0xffffffffu, rs1, 1);
        rs1 += __shfl_xor_sync(0xffffffffu, rs1, 2);
        float e0 = __expf(m0 - mn0), e1 = __expf(m1 - mn1);
        l0 = l0 * e0 + rs0; l1 = l1 * e1 + rs1;
        m0 = mn0; m1 = mn1;
        #pragma unroll
        for (int nt = 0; nt < 4; nt++) {
            o[nt][0] *= e0; o[nt][1] *= e0;
            o[nt][2] *= e1; o[nt][3] *= e1;
        }
        __syncwarp();

        #pragma unroll
        for (int ks = 0; ks < 8; ks++) {
            unsigned af[4];
            af[0] = Ps[wq + gid][ks * 8 + tig];
            af[1] = Ps[wq + gid + 8][ks * 8 + tig];
            af[2] = Ps[wq + gid][ks * 8 + tig + 4];
            af[3] = Ps[wq + gid + 8][ks * 8 + tig + 4];
            #pragma unroll
            for (int nt = 0; nt < 4; nt++) {
                unsigned bf[2];
                bf[0] = Vs[ks * 8 + tig][nt * 8 + gid];
                bf[1] = Vs[ks * 8 + tig + 4][nt * 8 + gid];
                mma8(o[nt], af, bf);
            }
        }
    }

    float i0 = 1.f / l0, i1 = 1.f / l1;
    long row0 = (long)(b * 1024 + q0 + wq + gid);
    #pragma unroll
    for (int nt = 0; nt < 4; nt++) {
        int col = h * 32 + nt * 8 + 2 * tig;
        *(float2*)&out[row0 * 256 + col]       = make_float2(o[nt][0] * i0, o[nt][1] * i0);
        *(float2*)&out[(row0 + 8) * 256 + col] = make_float2(o[nt][2] * i1, o[nt][3] * i1);
    }
}

// ---------------- residual + layernorm (general) ----------------
__global__ void resln_k(const float* __restrict__ a, const float* __restrict__ b,
                        const float* __restrict__ c, const float* __restrict__ cb,
                        const float* __restrict__ g, const float* __restrict__ be,
                        float* __restrict__ out,
                        const float* __restrict__ pos, float* __restrict__ out2)
{
    __shared__ float sm[8];
    int row = blockIdx.x, t = threadIdx.x;
    long off = (long)row * NC + t;
    float x = a[off] + b[off];
    if (c)  x += c[off];
    if (cb) x += cb[t];
    float mn = blockSum256(x, sm) * (1.f / NC);
    float d = x - mn;
    float v = blockSum256(d * d, sm) * (1.f / NC);
    float y = d * rsqrtf(v + 1e-5f) * g[t] + be[t];
    out[off] = y;
    if (out2) out2[off] = y + pos[off];
}

// ---------------- deformable sampling (branch-free, batched gathers) ----------------
__global__ void deform_k(const float* __restrict__ value,
                         const float* __restrict__ offaw,
                         const float* __restrict__ refp,
                         float* __restrict__ out)
{
    int gw   = (blockIdx.x * blockDim.x + threadIdx.x) >> 5;
    int lane = threadIdx.x & 31;
    int h  = gw & 7;
    int bq = gw >> 3;
    int b  = bq >> 10;

    const float* ap = offaw + (long)bq * 384 + 256 + h * 16;
    float w[16];
    float mx = -3.4e38f;
    #pragma unroll
    for (int j = 0; j < 16; j++) { w[j] = ap[j]; mx = fmaxf(mx, w[j]); }
    float s = 0.f;
    #pragma unroll
    for (int j = 0; j < 16; j++) { w[j] = __expf(w[j] - mx); s += w[j]; }
    float inv = 1.f / s;

    const float* op = offaw + (long)bq * 384 + h * 32;
    const float* rp = refp + (long)bq * 8;
    const float* vb = value + (long)b * NLSRC * NC + h * NDH + lane;

    const int wl_[4] = {128, 64, 32, 16};
    const int st_[4] = {0, 16384, 20480, 21504};

    float acc = 0.f;
    #pragma unroll
    for (int l = 0; l < 4; l++) {
        const int W = wl_[l];
        const int st = st_[l];
        float rx = rp[l * 2 + 0] * (float)W - 0.5f;
        float ry = rp[l * 2 + 1] * (float)W - 0.5f;

        int   offs[4][4];
        float wts[4][4];
        #pragma unroll
        for (int p = 0; p < 4; p++) {
            float a = w[l * 4 + p] * inv;
            float x = rx + op[(l * 4 + p) * 2 + 0];
            float y = ry + op[(l * 4 + p) * 2 + 1];
            float xf = floorf(x), yf = floorf(y);
            int x0 = (int)xf, y0 = (int)yf;
            float wx1 = x - xf, wx0 = 1.f - wx1;
            float wy1 = y - yf, wy0 = 1.f - wy1;
            int x1 = x0 + 1, y1 = y0 + 1;
            int xc0 = min(max(x0, 0), W - 1), xc1 = min(max(x1, 0), W - 1);
            int yc0 = min(max(y0, 0), W - 1), yc1 = min(max(y1, 0), W - 1);
            float vx0 = (x0 >= 0 && x0 < W) ? 1.f : 0.f;
            float vx1 = (x1 >= 0 && x1 < W) ? 1.f : 0.f;
            float vy0 = (y0 >= 0 && y0 < W) ? 1.f : 0.f;
            float vy1 = (y1 >= 0 && y1 < W) ? 1.f : 0.f;
            offs[p][0] = st + yc0 * W + xc0;  wts[p][0] = a * wy0 * wx0 * vy0 * vx0;
            offs[p][1] = st + yc0 * W + xc1;  wts[p][1] = a * wy0 * wx1 * vy0 * vx1;
            offs[p][2] = st + yc1 * W + xc0;  wts[p][2] = a * wy1 * wx0 * vy1 * vx0;
            offs[p][3] = st + yc1 * W + xc1;  wts[p][3] = a * wy1 * wx1 * vy1 * vx1;
        }
        float g[4][4];
        #pragma unroll
        for (int p = 0; p < 4; p++)
            #pragma unroll
            for (int c2 = 0; c2 < 4; c2++)
                g[p][c2] = vb[(long)offs[p][c2] * NC];
        #pragma unroll
        for (int p = 0; p < 4; p++)
            #pragma unroll
            for (int c2 = 0; c2 < 4; c2++)
                acc = fmaf(wts[p][c2], g[p][c2], acc);
    }
    out[(long)bq * NC + h * NDH + lane] = acc;
}

extern "C" void kernel_launch(void* const* d_in, const int* in_sizes, int n_in,
                              void* d_out, int out_size)
{
    const float* tgt   = (const float*)d_in[0];
    const float* qpos  = (const float*)d_in[1];
    const float* refp  = (const float*)d_in[2];
    const float* src   = (const float*)d_in[3];
    const float* in_w  = (const float*)d_in[4];
    const float* in_b  = (const float*)d_in[5];
    const float* sa_w  = (const float*)d_in[6];
    const float* sa_b  = (const float*)d_in[7];
    const float* off_w = (const float*)d_in[8];
    const float* off_b = (const float*)d_in[9];
    const float* aw_w  = (const float*)d_in[10];
    const float* aw_b  = (const float*)d_in[11];
    const float* val_w = (const float*)d_in[12];
    const float* val_b = (const float*)d_in[13];
    const float* co_w  = (const float*)d_in[14];
    const float* co_b  = (const float*)d_in[15];
    const float* ln1_g = (const float*)d_in[16];
    const float* ln1_b = (const float*)d_in[17];
    const float* ln2_g = (const float*)d_in[18];
    const float* ln2_b = (const float*)d_in[19];
    const float* ln3_g = (const float*)d_in[20];
    const float* ln3_b = (const float*)d_in[21];
    const float* f1_w  = (const float*)d_in[22];
    const float* f1_b  = (const float*)d_in[23];
    const float* f2_w  = (const float*)d_in[24];
    const float* f2_b  = (const float*)d_in[25];

    float* S = nullptr;
    cudaGetSymbolAddress((void**)&S, g_scratch);

    float* qk    = S + OFF_QK;
    float* qkb   = S + OFF_QKB;
    float* vbw   = S + OFF_VBW;
    float* att   = S + OFF_ATT;
    float* tmp   = S + OFF_TMP;
    float* tmp2  = S + OFF_TMP2;
    float* tgt1  = S + OFF_TGT1;
    float* xq    = S + OFF_X;
    float* offaw = S + OFF_OFFAW;
    float* samp  = S + OFF_SAMP;
    float* tgt2  = S + OFF_TGT2;
    float* ffn1  = S + OFF_FFN1;
    float* wcat  = S + OFF_WCAT;
    float* valb  = S + OFF_VAL;

    // ---- self-attention ----
    add_k<<<4096, 256>>>(tgt, qpos, qk, NB * NLQ * NC);
    wcat_k<<<(384 * 256 + 384 + 255) / 256, 256>>>(off_w, aw_w, off_b, aw_b, wcat);

    // merged q|k|v projection: z=0:q, z=1:k, z=2:v  (zdiv=2 -> zo = 0,0,1; zi = 0,1,0)
    gemmtc_k<false><<<dim3(2, 32, 3), 256>>>(
        qk, in_w, in_b, qkb, 256, 256, 256, 512,
        2,
        (long)(tgt - qk),
        131072, 65536,
        (long)(vbw - qkb), 256,
        512, 256);

    // fused attention (scores + softmax + PV), tf32 tensor cores
    flashtc_k<<<dim3(16, 1, 32), 128>>>(qkb, vbw, att);

    // out projection + residual + LN2
    gemmtc_k<false><<<dim3(2, 32, 1), 256>>>(
        att, sa_w, sa_b, tmp, 256, 256, 256, 256, 1, 0, 0, 0, 0, 0, 0, 0);
    resln_k<<<4096, 256>>>(tgt, tmp, nullptr, nullptr, ln2_g, ln2_b, tgt1, qpos, xq);

    // ---- deformable cross-attention ----
    gemmtc_k<false><<<dim3(2, 680, 1), 256>>>(
        src, val_w, val_b, valb, 256, 256, 256, 256, 1, 0, 0, 0, 0, 0, 0, 0);
    // fused offsets + aw logits: N=384
    gemmtc_k<false><<<dim3(3, 32, 1), 256>>>(
        xq, wcat, wcat + 384 * 256, offaw, 256, 256, 256, 384, 1, 0, 0, 0, 0, 0, 0, 0);

    deform_k<<<4096, 256>>>(valb, offaw, refp, samp);

    gemmtc_k<false><<<dim3(2, 32, 1), 256>>>(
        samp, co_w, co_b, tmp, 256, 256, 256, 256, 1, 0, 0, 0, 0, 0, 0, 0);
    resln_k<<<4096, 256>>>(tgt1, tmp, nullptr, nullptr, ln1_g, ln1_b, tgt2, nullptr, nullptr);

    // ---- FFN ----
    gemmtc_k<true><<<dim3(8, 32, 1), 256>>>(
        tgt2, f1_w, f1_b, ffn1, 256, 256, 256, 1024, 1, 0, 0, 0, 0, 0, 0, 0);
    // ffn2 split-K=2: z=0 -> tmp (K 0..511), z=1 -> tmp2 (K 512..1023)
    gemmtc_k<false><<<dim3(2, 32, 2), 256>>>(
        ffn1, f2_w, nullptr, tmp, 512, 1024, 1024, 256,
        1,
        512,
        512, 0,
        (long)(tmp2 - tmp), 0,
        0, 0);
    resln_k<<<4096, 256>>>(tgt2, tmp, tmp2, f2_b, ln3_g, ln3_b, (float*)d_out, nullptr, nullptr);
}